// round 4
// baseline (speedup 1.0000x reference)
#include <cuda_runtime.h>

#define BATCH 8
#define CH 64
#define NPTS 65536
#define RR 32
#define NVOX 32768  // 32^3

// ---------------- scratch (__device__ globals; no allocation allowed) ------
__device__ float d_mean[BATCH * 3];
__device__ float d_scale[BATCH];
__device__ float d_voxc[BATCH * 3 * NPTS];          // clipped voxel coords (for devox)
__device__ float d_cnt[BATCH * NVOX];               // per-voxel point counts
__device__ float d_grid0[(size_t)BATCH * NVOX * CH]; // NDHWC voxel grid (scatter sums -> avg)
__device__ float d_grid1[(size_t)BATCH * NVOX * CH]; // after conv1
__device__ float d_grid2[(size_t)BATCH * NVOX * CH]; // after conv2
__device__ float d_wT1[27 * 64 * 64];               // [tap][ic][oc], BN-scale folded
__device__ float d_wT2[27 * 64 * 64];
__device__ float d_biasE1[64];
__device__ float d_biasE2[64];

// ---------------- zero scratch each launch (graph replays!) ----------------
__global__ void zero_kernel() {
    size_t t = (size_t)blockIdx.x * 256 + threadIdx.x;
    const size_t g4 = (size_t)BATCH * NVOX * CH / 4;   // 4194304 float4s
    float4 z = make_float4(0.f, 0.f, 0.f, 0.f);
    if (t < g4) {
        reinterpret_cast<float4*>(d_grid0)[t] = z;
    } else {
        size_t u = t - g4;
        if (u < (size_t)BATCH * NVOX / 4) reinterpret_cast<float4*>(d_cnt)[u] = z;
    }
}

// ---------------- per-batch coords mean ------------------------------------
__global__ void mean_kernel(const float* __restrict__ coords) {
    int b = blockIdx.x, tid = threadIdx.x;
    const float* cb = coords + (size_t)b * 3 * NPTS;
    float s0 = 0.f, s1 = 0.f, s2 = 0.f;
    for (int n = tid; n < NPTS; n += 256) {
        s0 += cb[n];
        s1 += cb[NPTS + n];
        s2 += cb[2 * NPTS + n];
    }
    __shared__ float sh[3][256];
    sh[0][tid] = s0; sh[1][tid] = s1; sh[2][tid] = s2;
    __syncthreads();
    for (int off = 128; off > 0; off >>= 1) {
        if (tid < off) {
            sh[0][tid] += sh[0][tid + off];
            sh[1][tid] += sh[1][tid + off];
            sh[2][tid] += sh[2][tid + off];
        }
        __syncthreads();
    }
    if (tid == 0) {
        d_mean[b * 3 + 0] = sh[0][0] / (float)NPTS;
        d_mean[b * 3 + 1] = sh[1][0] / (float)NPTS;
        d_mean[b * 3 + 2] = sh[2][0] / (float)NPTS;
    }
}

// ---------------- per-batch max point radius -------------------------------
__global__ void scale_kernel(const float* __restrict__ coords) {
    int b = blockIdx.x, tid = threadIdx.x;
    const float* cb = coords + (size_t)b * 3 * NPTS;
    float m0 = d_mean[b * 3 + 0], m1 = d_mean[b * 3 + 1], m2 = d_mean[b * 3 + 2];
    float mx = 0.f;
    for (int n = tid; n < NPTS; n += 256) {
        float dx = cb[n] - m0;
        float dy = cb[NPTS + n] - m1;
        float dz = cb[2 * NPTS + n] - m2;
        mx = fmaxf(mx, dx * dx + dy * dy + dz * dz);
    }
    __shared__ float sh[256];
    sh[tid] = mx;
    __syncthreads();
    for (int off = 128; off > 0; off >>= 1) {
        if (tid < off) sh[tid] = fmaxf(sh[tid], sh[tid + off]);
        __syncthreads();
    }
    if (tid == 0) d_scale[b] = sqrtf(sh[0]);
}

// ---------------- weight transpose + BN fold -------------------------------
// wT[(tap*64+ic)*64+oc] = w[oc][ic][tap] * g[oc]/sqrt(v[oc]+eps)
// biasE[oc] = (b[oc]-m[oc])*g[oc]/sqrt(v[oc]+eps) + be[oc]
__global__ void prep_kernel(const float* __restrict__ w, const float* __restrict__ bias,
                            const float* __restrict__ g, const float* __restrict__ be,
                            const float* __restrict__ m, const float* __restrict__ v,
                            float* __restrict__ wT, float* __restrict__ biasE) {
    int i = blockIdx.x * 256 + threadIdx.x;
    if (i < 64) {
        float sc = g[i] * rsqrtf(v[i] + 1e-4f);
        biasE[i] = (bias[i] - m[i]) * sc + be[i];
    }
    if (i < 27 * 64 * 64) {
        int oc = i & 63;
        int ic = (i >> 6) & 63;
        int tap = i >> 12;
        float sc = g[oc] * rsqrtf(v[oc] + 1e-4f);
        wT[i] = w[(oc * 64 + ic) * 27 + tap] * sc;
    }
}

// ---------------- voxelize: normalize coords + scatter-add -----------------
__global__ void scatter_kernel(const float* __restrict__ coords,
                               const float* __restrict__ feats) {
    int t = blockIdx.x * 256 + threadIdx.x;       // t in [0, BATCH*NPTS)
    int b = t >> 16;
    int n = t & (NPTS - 1);
    const float* cb = coords + (size_t)b * 3 * NPTS;
    float m0 = d_mean[b * 3 + 0], m1 = d_mean[b * 3 + 1], m2 = d_mean[b * 3 + 2];
    float den = d_scale[b] * 2.0f;

    float vx = fminf(fmaxf(((cb[n]            - m0) / den + 0.5f) * 32.0f, 0.f), 31.f);
    float vy = fminf(fmaxf(((cb[NPTS + n]     - m1) / den + 0.5f) * 32.0f, 0.f), 31.f);
    float vz = fminf(fmaxf(((cb[2 * NPTS + n] - m2) / den + 0.5f) * 32.0f, 0.f), 31.f);

    float* vout = d_voxc + (size_t)b * 3 * NPTS;
    vout[n] = vx;
    vout[NPTS + n] = vy;
    vout[2 * NPTS + n] = vz;

    int ix = (int)rintf(vx);   // round-half-even, matches jnp.round
    int iy = (int)rintf(vy);
    int iz = (int)rintf(vz);
    int idx = (ix * 32 + iy) * 32 + iz;

    atomicAdd(&d_cnt[b * NVOX + idx], 1.0f);
    float* gb = &d_grid0[((size_t)b * NVOX + idx) * CH];
    const float* fb = feats + (size_t)b * CH * NPTS + n;
#pragma unroll 8
    for (int c = 0; c < CH; c++)
        atomicAdd(&gb[c], fb[(size_t)c * NPTS]);
}

// ---------------- divide sums by counts ------------------------------------
__global__ void avg_kernel() {
    int t = blockIdx.x * 256 + threadIdx.x;   // t in [0, BATCH*NVOX*16)
    int vox = t >> 4;
    int c4 = t & 15;
    float inv = 1.0f / fmaxf(d_cnt[vox], 1.0f);
    float4* p = reinterpret_cast<float4*>(&d_grid0[(size_t)vox * CH + c4 * 4]);
    float4 x = *p;
    x.x *= inv; x.y *= inv; x.z *= inv; x.w *= inv;
    *p = x;
}

// ---------------- 3x3x3 conv 64->64 + folded BN + LeakyReLU ----------------
// NDHWC. Block: 4x4x8 voxel tile, all 64 oc. 256 threads, each: 8 voxels x 4 oc.
#define TTX 4
#define TTY 4
#define TTZ 8
#define HVOX 360              // 6*6*10 halo voxels
#define INSTRIDE 68           // 64 ch padded for bank spread + float4 alignment
#define IN_SH_FLOATS (HVOX * INSTRIDE)   // 24480
#define W_SH_FLOATS (64 * 64)            // 4096
#define CONV_SMEM ((IN_SH_FLOATS + W_SH_FLOATS) * 4)

__global__ void __launch_bounds__(256) conv_kernel(const float* __restrict__ gin,
                                                   float* __restrict__ gout,
                                                   const float* __restrict__ wT,
                                                   const float* __restrict__ biasE) {
    extern __shared__ float sh[];
    float* in_sh = sh;
    float* w_sh = sh + IN_SH_FLOATS;
    int tid = threadIdx.x;
    int bx = blockIdx.x;
    int b = bx >> 8;              // 256 tiles per batch
    int tile = bx & 255;
    int tz = tile & 3;
    int ty = (tile >> 2) & 7;
    int txi = tile >> 5;
    int x0 = txi * TTX, y0 = ty * TTY, z0 = tz * TTZ;

    // load 6x6x10 halo tile, zero-padded
    for (int s = tid; s < HVOX * 16; s += 256) {
        int vox = s >> 4, c4 = s & 15;
        int hz = vox % 10;
        int tmp = vox / 10;
        int hy = tmp % 6;
        int hx = tmp / 6;
        int gx = x0 + hx - 1, gy = y0 + hy - 1, gz = z0 + hz - 1;
        float4 val = make_float4(0.f, 0.f, 0.f, 0.f);
        if ((unsigned)gx < 32u && (unsigned)gy < 32u && (unsigned)gz < 32u)
            val = *reinterpret_cast<const float4*>(
                &gin[((((size_t)b * 32 + gx) * 32 + gy) * 32 + gz) * CH + c4 * 4]);
        *reinterpret_cast<float4*>(&in_sh[vox * INSTRIDE + c4 * 4]) = val;
    }

    int vg = tid & 15, og = tid >> 4;
    int lx = vg >> 2, ly = vg & 3;
    int oc0 = og * 4;

    float acc[8][4];
#pragma unroll
    for (int v = 0; v < 8; v++)
#pragma unroll
        for (int j = 0; j < 4; j++) acc[v][j] = 0.f;

    for (int tap = 0; tap < 27; tap++) {
        __syncthreads();   // (first iter: also fences halo load; later: protects w_sh)
        {
            const float4* wsrc = reinterpret_cast<const float4*>(wT + tap * 4096);
            float4* wdst = reinterpret_cast<float4*>(w_sh);
            for (int i = tid; i < 1024; i += 256) wdst[i] = wsrc[i];
        }
        __syncthreads();
        int dxi = tap / 9;
        int rr = tap - dxi * 9;
        int dyi = rr / 3;
        int dzi = rr - dyi * 3;
        const float* ip = &in_sh[(((lx + dxi) * 6 + (ly + dyi)) * 10 + dzi) * INSTRIDE];
#pragma unroll 4
        for (int ic4 = 0; ic4 < 16; ic4++) {
            float4 a[8];
#pragma unroll
            for (int v = 0; v < 8; v++)
                a[v] = *reinterpret_cast<const float4*>(&ip[v * INSTRIDE + ic4 * 4]);
#pragma unroll
            for (int j = 0; j < 4; j++) {
                float4 wv = *reinterpret_cast<const float4*>(
                    &w_sh[((ic4 * 4 + j) << 6) + oc0]);
#pragma unroll
                for (int v = 0; v < 8; v++) {
                    float av = (j == 0) ? a[v].x : (j == 1) ? a[v].y
                             : (j == 2) ? a[v].z : a[v].w;
                    acc[v][0] += av * wv.x;
                    acc[v][1] += av * wv.y;
                    acc[v][2] += av * wv.z;
                    acc[v][3] += av * wv.w;
                }
            }
        }
    }

    float bb0 = biasE[oc0], bb1 = biasE[oc0 + 1], bb2 = biasE[oc0 + 2], bb3 = biasE[oc0 + 3];
#pragma unroll
    for (int v = 0; v < 8; v++) {
        float y0v = acc[v][0] + bb0;
        float y1v = acc[v][1] + bb1;
        float y2v = acc[v][2] + bb2;
        float y3v = acc[v][3] + bb3;
        y0v = (y0v >= 0.f) ? y0v : 0.1f * y0v;
        y1v = (y1v >= 0.f) ? y1v : 0.1f * y1v;
        y2v = (y2v >= 0.f) ? y2v : 0.1f * y2v;
        y3v = (y3v >= 0.f) ? y3v : 0.1f * y3v;
        size_t o = ((((size_t)b * 32 + (x0 + lx)) * 32 + (y0 + ly)) * 32 + (z0 + v)) * CH + oc0;
        *reinterpret_cast<float4*>(&gout[o]) = make_float4(y0v, y1v, y2v, y3v);
    }
}

// ---------------- trilinear devoxelize -> point features -------------------
__global__ void devox_kernel(float* __restrict__ out, const float* __restrict__ grid) {
    int n = blockIdx.x * 256 + threadIdx.x;
    int cg = blockIdx.y;     // 16 channel-groups of 4
    int b = blockIdx.z;
    const float* vc = d_voxc + (size_t)b * 3 * NPTS;
    float cx = vc[n], cy = vc[NPTS + n], cz = vc[2 * NPTS + n];
    int ix0 = (int)floorf(cx), iy0 = (int)floorf(cy), iz0 = (int)floorf(cz);
    float fx = cx - (float)ix0, fy = cy - (float)iy0, fz = cz - (float)iz0;
    int ix1 = min(ix0 + 1, 31), iy1 = min(iy0 + 1, 31), iz1 = min(iz0 + 1, 31);
    float gx0 = 1.f - fx, gy0 = 1.f - fy, gz0 = 1.f - fz;

    const float* g = grid + ((size_t)b * NVOX) * CH + cg * 4;
    float4 acc = make_float4(0.f, 0.f, 0.f, 0.f);

#define CORNER(XI, YI, ZI, W)                                                        \
    {                                                                                \
        float4 cv = *reinterpret_cast<const float4*>(                                \
            &g[(size_t)(((XI) * 32 + (YI)) * 32 + (ZI)) * CH]);                      \
        float ww = (W);                                                              \
        acc.x += ww * cv.x; acc.y += ww * cv.y; acc.z += ww * cv.z; acc.w += ww * cv.w; \
    }
    CORNER(ix0, iy0, iz0, gx0 * gy0 * gz0)
    CORNER(ix0, iy0, iz1, gx0 * gy0 * fz)
    CORNER(ix0, iy1, iz0, gx0 * fy * gz0)
    CORNER(ix0, iy1, iz1, gx0 * fy * fz)
    CORNER(ix1, iy0, iz0, fx * gy0 * gz0)
    CORNER(ix1, iy0, iz1, fx * gy0 * fz)
    CORNER(ix1, iy1, iz0, fx * fy * gz0)
    CORNER(ix1, iy1, iz1, fx * fy * fz)
#undef CORNER

    size_t ob = ((size_t)b * CH + cg * 4) * NPTS + n;
    out[ob] = acc.x;
    out[ob + NPTS] = acc.y;
    out[ob + 2 * (size_t)NPTS] = acc.z;
    out[ob + 3 * (size_t)NPTS] = acc.w;
}

// ---------------- echo coords into output tail -----------------------------
__global__ void copy_coords_kernel(float* __restrict__ out, const float* __restrict__ coords) {
    int t = blockIdx.x * 256 + threadIdx.x;   // t < BATCH*3*NPTS/4 = 393216
    reinterpret_cast<float4*>(out)[t] = reinterpret_cast<const float4*>(coords)[t];
}

// ---------------- launch ----------------------------------------------------
extern "C" void kernel_launch(void* const* d_in, const int* in_sizes, int n_in,
                              void* d_out, int out_size) {
    (void)in_sizes; (void)n_in; (void)out_size;
    const float* feats  = (const float*)d_in[0];
    const float* coords = (const float*)d_in[1];
    const float* w1  = (const float*)d_in[2];
    const float* b1  = (const float*)d_in[3];
    const float* g1  = (const float*)d_in[4];
    const float* be1 = (const float*)d_in[5];
    const float* m1  = (const float*)d_in[6];
    const float* v1  = (const float*)d_in[7];
    const float* w2  = (const float*)d_in[8];
    const float* b2  = (const float*)d_in[9];
    const float* g2  = (const float*)d_in[10];
    const float* be2 = (const float*)d_in[11];
    const float* m2  = (const float*)d_in[12];
    const float* v2  = (const float*)d_in[13];
    float* out = (float*)d_out;

    float *p_g0, *p_g1, *p_g2, *p_wT1, *p_wT2, *p_be1, *p_be2;
    cudaGetSymbolAddress((void**)&p_g0, d_grid0);
    cudaGetSymbolAddress((void**)&p_g1, d_grid1);
    cudaGetSymbolAddress((void**)&p_g2, d_grid2);
    cudaGetSymbolAddress((void**)&p_wT1, d_wT1);
    cudaGetSymbolAddress((void**)&p_wT2, d_wT2);
    cudaGetSymbolAddress((void**)&p_be1, d_biasE1);
    cudaGetSymbolAddress((void**)&p_be2, d_biasE2);

    cudaFuncSetAttribute(conv_kernel, cudaFuncAttributeMaxDynamicSharedMemorySize, CONV_SMEM);

    zero_kernel<<<16640, 256>>>();
    mean_kernel<<<BATCH, 256>>>(coords);
    scale_kernel<<<BATCH, 256>>>(coords);
    prep_kernel<<<(27 * 64 * 64 + 255) / 256, 256>>>(w1, b1, g1, be1, m1, v1, p_wT1, p_be1);
    prep_kernel<<<(27 * 64 * 64 + 255) / 256, 256>>>(w2, b2, g2, be2, m2, v2, p_wT2, p_be2);
    scatter_kernel<<<(BATCH * NPTS) / 256, 256>>>(coords, feats);
    avg_kernel<<<(BATCH * NVOX * 16) / 256, 256>>>();
    conv_kernel<<<BATCH * 256, 256, CONV_SMEM>>>(p_g0, p_g1, p_wT1, p_be1);
    conv_kernel<<<BATCH * 256, 256, CONV_SMEM>>>(p_g1, p_g2, p_wT2, p_be2);
    devox_kernel<<<dim3(NPTS / 256, 16, BATCH), 256>>>(out, p_g2);
    copy_coords_kernel<<<(BATCH * 3 * NPTS / 4) / 256, 256>>>(
        out + (size_t)BATCH * CH * NPTS, coords);
}

// round 5
// speedup vs baseline: 1.5090x; 1.5090x over previous
#include <cuda_runtime.h>

#define BATCH 8
#define CH 64
#define NPTS 65536
#define RR 32
#define NVOX 32768  // 32^3

// ---------------- scratch (__device__ globals; no allocation allowed) ------
__device__ float d_mean[BATCH * 3];
__device__ float d_scale[BATCH];
__device__ float d_voxc[BATCH * 3 * NPTS];            // clipped voxel coords (for devox)
__device__ float d_cnt[BATCH * NVOX];                 // per-voxel point counts
__device__ float d_featsT[(size_t)BATCH * NPTS * CH]; // point-major features
__device__ float d_grid0[(size_t)BATCH * NVOX * CH];  // NDHWC voxel grid
__device__ float d_grid1[(size_t)BATCH * NVOX * CH];  // after conv1
__device__ float d_grid2[(size_t)BATCH * NVOX * CH];  // after conv2
__device__ float d_wT1[27 * 64 * 64];                 // [tap][ic][oc], BN folded
__device__ float d_wT2[27 * 64 * 64];
__device__ float d_biasE1[64];
__device__ float d_biasE2[64];

// ---------------- f32x2 packed helpers -------------------------------------
__device__ __forceinline__ unsigned long long fma2(unsigned long long a,
                                                   unsigned long long b,
                                                   unsigned long long c) {
    unsigned long long d;
    asm("fma.rn.f32x2 %0, %1, %2, %3;" : "=l"(d) : "l"(a), "l"(b), "l"(c));
    return d;
}
__device__ __forceinline__ unsigned long long bcast2(float x) {
    unsigned long long d;
    asm("mov.b64 %0, {%1, %1};" : "=l"(d) : "f"(x));
    return d;
}
__device__ __forceinline__ float2 unpack2(unsigned long long v) {
    float2 r;
    asm("mov.b64 {%0, %1}, %2;" : "=f"(r.x), "=f"(r.y) : "l"(v));
    return r;
}

// ---------------- zero scratch each launch (graph replays!) ----------------
__global__ void zero_kernel() {
    size_t t = (size_t)blockIdx.x * 256 + threadIdx.x;
    const size_t g4 = (size_t)BATCH * NVOX * CH / 4;   // 4194304 float4s
    float4 z = make_float4(0.f, 0.f, 0.f, 0.f);
    if (t < g4) {
        reinterpret_cast<float4*>(d_grid0)[t] = z;
    } else {
        size_t u = t - g4;
        if (u < (size_t)BATCH * NVOX / 4) reinterpret_cast<float4*>(d_cnt)[u] = z;
    }
}

// ---------------- per-batch coords mean ------------------------------------
__global__ void mean_kernel(const float* __restrict__ coords) {
    int b = blockIdx.x, tid = threadIdx.x;
    const float* cb = coords + (size_t)b * 3 * NPTS;
    float s0 = 0.f, s1 = 0.f, s2 = 0.f;
    for (int n = tid; n < NPTS; n += 256) {
        s0 += cb[n];
        s1 += cb[NPTS + n];
        s2 += cb[2 * NPTS + n];
    }
    __shared__ float sh[3][256];
    sh[0][tid] = s0; sh[1][tid] = s1; sh[2][tid] = s2;
    __syncthreads();
    for (int off = 128; off > 0; off >>= 1) {
        if (tid < off) {
            sh[0][tid] += sh[0][tid + off];
            sh[1][tid] += sh[1][tid + off];
            sh[2][tid] += sh[2][tid + off];
        }
        __syncthreads();
    }
    if (tid == 0) {
        d_mean[b * 3 + 0] = sh[0][0] / (float)NPTS;
        d_mean[b * 3 + 1] = sh[1][0] / (float)NPTS;
        d_mean[b * 3 + 2] = sh[2][0] / (float)NPTS;
    }
}

// ---------------- per-batch max point radius -------------------------------
__global__ void scale_kernel(const float* __restrict__ coords) {
    int b = blockIdx.x, tid = threadIdx.x;
    const float* cb = coords + (size_t)b * 3 * NPTS;
    float m0 = d_mean[b * 3 + 0], m1 = d_mean[b * 3 + 1], m2 = d_mean[b * 3 + 2];
    float mx = 0.f;
    for (int n = tid; n < NPTS; n += 256) {
        float dx = cb[n] - m0;
        float dy = cb[NPTS + n] - m1;
        float dz = cb[2 * NPTS + n] - m2;
        mx = fmaxf(mx, dx * dx + dy * dy + dz * dz);
    }
    __shared__ float sh[256];
    sh[tid] = mx;
    __syncthreads();
    for (int off = 128; off > 0; off >>= 1) {
        if (tid < off) sh[tid] = fmaxf(sh[tid], sh[tid + off]);
        __syncthreads();
    }
    if (tid == 0) d_scale[b] = sqrtf(sh[0]);
}

// ---------------- weight transpose + BN fold -------------------------------
__global__ void prep_kernel(const float* __restrict__ w, const float* __restrict__ bias,
                            const float* __restrict__ g, const float* __restrict__ be,
                            const float* __restrict__ m, const float* __restrict__ v,
                            float* __restrict__ wT, float* __restrict__ biasE) {
    int i = blockIdx.x * 256 + threadIdx.x;
    if (i < 64) {
        float sc = g[i] * rsqrtf(v[i] + 1e-4f);
        biasE[i] = (bias[i] - m[i]) * sc + be[i];
    }
    if (i < 27 * 64 * 64) {
        int oc = i & 63;
        int ic = (i >> 6) & 63;
        int tap = i >> 12;
        float sc = g[oc] * rsqrtf(v[oc] + 1e-4f);
        wT[i] = w[(oc * 64 + ic) * 27 + tap] * sc;
    }
}

// ---------------- features transpose: [b][c][n] -> [b][n][c] ----------------
__global__ void transpose_kernel(const float* __restrict__ f) {
    __shared__ float tile[32][33];
    int b = blockIdx.z;
    int c0 = blockIdx.y * 32;
    int n0 = blockIdx.x * 32;
    int tx = threadIdx.x, ty = threadIdx.y;   // 32 x 8
    const float* fb = f + (size_t)b * CH * NPTS;
#pragma unroll
    for (int i = 0; i < 4; i++) {
        int c = c0 + ty + i * 8;
        tile[ty + i * 8][tx] = fb[(size_t)c * NPTS + n0 + tx];
    }
    __syncthreads();
#pragma unroll
    for (int i = 0; i < 4; i++) {
        int n = n0 + ty + i * 8;
        d_featsT[((size_t)b * NPTS + n) * CH + c0 + tx] = tile[tx][ty + i * 8];
    }
}

// ---------------- voxelize: normalize coords + vectorized scatter-add ------
__global__ void scatter_kernel(const float* __restrict__ coords) {
    int t = blockIdx.x * 256 + threadIdx.x;       // t in [0, BATCH*NPTS)
    int b = t >> 16;
    int n = t & (NPTS - 1);
    const float* cb = coords + (size_t)b * 3 * NPTS;
    float m0 = d_mean[b * 3 + 0], m1 = d_mean[b * 3 + 1], m2 = d_mean[b * 3 + 2];
    float den = d_scale[b] * 2.0f;

    float vx = fminf(fmaxf(((cb[n]            - m0) / den + 0.5f) * 32.0f, 0.f), 31.f);
    float vy = fminf(fmaxf(((cb[NPTS + n]     - m1) / den + 0.5f) * 32.0f, 0.f), 31.f);
    float vz = fminf(fmaxf(((cb[2 * NPTS + n] - m2) / den + 0.5f) * 32.0f, 0.f), 31.f);

    float* vout = d_voxc + (size_t)b * 3 * NPTS;
    vout[n] = vx;
    vout[NPTS + n] = vy;
    vout[2 * NPTS + n] = vz;

    int ix = (int)rintf(vx);   // round-half-even, matches jnp.round
    int iy = (int)rintf(vy);
    int iz = (int)rintf(vz);
    int idx = (ix * 32 + iy) * 32 + iz;

    atomicAdd(&d_cnt[b * NVOX + idx], 1.0f);
    float* gb = &d_grid0[((size_t)b * NVOX + idx) * CH];
    const float4* src = reinterpret_cast<const float4*>(
        d_featsT + ((size_t)b * NPTS + n) * CH);
#pragma unroll
    for (int c4 = 0; c4 < 16; c4++) {
        float4 f = src[c4];
        asm volatile("red.global.add.v4.f32 [%0], {%1, %2, %3, %4};"
                     :: "l"(gb + c4 * 4), "f"(f.x), "f"(f.y), "f"(f.z), "f"(f.w)
                     : "memory");
    }
}

// ---------------- divide sums by counts ------------------------------------
__global__ void avg_kernel() {
    int t = blockIdx.x * 256 + threadIdx.x;   // t in [0, BATCH*NVOX*16)
    int vox = t >> 4;
    int c4 = t & 15;
    float inv = 1.0f / fmaxf(d_cnt[vox], 1.0f);
    float4* p = reinterpret_cast<float4*>(&d_grid0[(size_t)vox * CH + c4 * 4]);
    float4 x = *p;
    x.x *= inv; x.y *= inv; x.z *= inv; x.w *= inv;
    *p = x;
}

// ---------------- 3x3x3 conv 64->64 + folded BN + LeakyReLU (f32x2) --------
// NDHWC. Block: 4x8x8 = 256 voxel tile, all 64 oc. 256 threads.
// Thread = (og, ly, lz): oc group of 8, y in [0,4), z in [0,8).
// Each thread: 8 voxels (vx in [0,4) x yh in {0,1} -> y = ly+4*yh) x 8 oc.
// Lanes of a warp differ in (ly, lz) with z contiguous -> LDS.128 N=4 optimal;
// warp shares og -> weight LDS is broadcast.
#define HVOX 600              // 6*10*10 halo voxels
#define INSTRIDE 68           // 64 ch padded: row step = 4 banks mod 32
#define IN_SH_FLOATS (HVOX * INSTRIDE)   // 40800
#define W_SH_FLOATS (64 * 64)            // 4096
#define CONV_SMEM ((IN_SH_FLOATS + W_SH_FLOATS) * 4)

__global__ void __launch_bounds__(256, 1) conv_kernel(const float* __restrict__ gin,
                                                      float* __restrict__ gout,
                                                      const float* __restrict__ wT,
                                                      const float* __restrict__ biasE) {
    extern __shared__ float sh[];
    float* in_sh = sh;
    float* w_sh = sh + IN_SH_FLOATS;
    int tid = threadIdx.x;
    int bx = blockIdx.x;
    int b = bx >> 7;              // 128 tiles per batch
    int tile = bx & 127;
    int tz = tile & 3;
    int ty = (tile >> 2) & 3;
    int txi = tile >> 4;          // [0,8)
    int x0 = txi * 4, y0 = ty * 8, z0 = tz * 8;

    // load 6x10x10 halo tile, zero-padded (coalesced: 16 float4 per row)
    for (int s = tid; s < HVOX * 16; s += 256) {
        int vox = s >> 4, c4 = s & 15;
        int hx = vox / 100;
        int r = vox - hx * 100;
        int hy = r / 10;
        int hz = r - hy * 10;
        int gx = x0 + hx - 1, gy = y0 + hy - 1, gz = z0 + hz - 1;
        float4 val = make_float4(0.f, 0.f, 0.f, 0.f);
        if ((unsigned)gx < 32u && (unsigned)gy < 32u && (unsigned)gz < 32u)
            val = *reinterpret_cast<const float4*>(
                &gin[((((size_t)b * 32 + gx) * 32 + gy) * 32 + gz) * CH + c4 * 4]);
        *reinterpret_cast<float4*>(&in_sh[vox * INSTRIDE + c4 * 4]) = val;
    }

    int og = tid >> 5;            // warp id = oc group
    int lane = tid & 31;
    int ly = lane >> 3;           // [0,4)
    int lz = lane & 7;            // [0,8)
    int oc0 = og * 8;

    unsigned long long acc2[8][4];
    const unsigned long long z2 = 0ull;
#pragma unroll
    for (int v = 0; v < 8; v++)
#pragma unroll
        for (int p = 0; p < 4; p++) acc2[v][p] = z2;

    // per-v halo row offsets: v = vx*2 + yh -> (vx*100 + yh*40) rows
    const int voff[8] = {0, 40 * INSTRIDE, 100 * INSTRIDE, 140 * INSTRIDE,
                         200 * INSTRIDE, 240 * INSTRIDE, 300 * INSTRIDE, 340 * INSTRIDE};

    for (int tap = 0; tap < 27; tap++) {
        __syncthreads();   // first iter: fences halo; later: protects w_sh reuse
        {
            const float4* wsrc = reinterpret_cast<const float4*>(wT + tap * 4096);
            float4* wdst = reinterpret_cast<float4*>(w_sh);
            for (int i = tid; i < 1024; i += 256) wdst[i] = wsrc[i];
        }
        __syncthreads();
        int dxi = tap / 9;
        int rr = tap - dxi * 9;
        int dyi = rr / 3;
        int dzi = rr - dyi * 3;
        const float* ip = &in_sh[((dxi * 10 + (ly + dyi)) * 10 + (lz + dzi)) * INSTRIDE];
#pragma unroll 4
        for (int ic4 = 0; ic4 < 16; ic4++) {
            float4 a[8];
#pragma unroll
            for (int v = 0; v < 8; v++)
                a[v] = *reinterpret_cast<const float4*>(&ip[voff[v] + ic4 * 4]);
#pragma unroll
            for (int j = 0; j < 4; j++) {
                const ulonglong2* wp = reinterpret_cast<const ulonglong2*>(
                    &w_sh[((ic4 * 4 + j) << 6) + oc0]);
                ulonglong2 wA = wp[0];   // oc pairs (0,1),(2,3)
                ulonglong2 wB = wp[1];   // oc pairs (4,5),(6,7)
#pragma unroll
                for (int v = 0; v < 8; v++) {
                    float av = (j == 0) ? a[v].x : (j == 1) ? a[v].y
                             : (j == 2) ? a[v].z : a[v].w;
                    unsigned long long a2 = bcast2(av);
                    acc2[v][0] = fma2(a2, wA.x, acc2[v][0]);
                    acc2[v][1] = fma2(a2, wA.y, acc2[v][1]);
                    acc2[v][2] = fma2(a2, wB.x, acc2[v][2]);
                    acc2[v][3] = fma2(a2, wB.y, acc2[v][3]);
                }
            }
        }
    }

    float4 bb0 = *reinterpret_cast<const float4*>(&biasE[oc0]);
    float4 bb1 = *reinterpret_cast<const float4*>(&biasE[oc0 + 4]);
#pragma unroll
    for (int v = 0; v < 8; v++) {
        int vx = v >> 1, yh = v & 1;
        float2 p0 = unpack2(acc2[v][0]);
        float2 p1 = unpack2(acc2[v][1]);
        float2 p2 = unpack2(acc2[v][2]);
        float2 p3 = unpack2(acc2[v][3]);
        float y[8] = {p0.x + bb0.x, p0.y + bb0.y, p1.x + bb0.z, p1.y + bb0.w,
                      p2.x + bb1.x, p2.y + bb1.y, p3.x + bb1.z, p3.y + bb1.w};
#pragma unroll
        for (int k = 0; k < 8; k++) y[k] = (y[k] >= 0.f) ? y[k] : 0.1f * y[k];
        size_t o = ((((size_t)b * 32 + (x0 + vx)) * 32 + (y0 + ly + 4 * yh)) * 32
                    + (z0 + lz)) * CH + oc0;
        *reinterpret_cast<float4*>(&gout[o]) = make_float4(y[0], y[1], y[2], y[3]);
        *reinterpret_cast<float4*>(&gout[o + 4]) = make_float4(y[4], y[5], y[6], y[7]);
    }
}

// ---------------- trilinear devoxelize -> point features -------------------
__global__ void devox_kernel(float* __restrict__ out, const float* __restrict__ grid) {
    int n = blockIdx.x * 256 + threadIdx.x;
    int cg = blockIdx.y;     // 16 channel-groups of 4
    int b = blockIdx.z;
    const float* vc = d_voxc + (size_t)b * 3 * NPTS;
    float cx = vc[n], cy = vc[NPTS + n], cz = vc[2 * NPTS + n];
    int ix0 = (int)floorf(cx), iy0 = (int)floorf(cy), iz0 = (int)floorf(cz);
    float fx = cx - (float)ix0, fy = cy - (float)iy0, fz = cz - (float)iz0;
    int ix1 = min(ix0 + 1, 31), iy1 = min(iy0 + 1, 31), iz1 = min(iz0 + 1, 31);
    float gx0 = 1.f - fx, gy0 = 1.f - fy, gz0 = 1.f - fz;

    const float* g = grid + ((size_t)b * NVOX) * CH + cg * 4;
    float4 acc = make_float4(0.f, 0.f, 0.f, 0.f);

#define CORNER(XI, YI, ZI, W)                                                        \
    {                                                                                \
        float4 cv = *reinterpret_cast<const float4*>(                                \
            &g[(size_t)(((XI) * 32 + (YI)) * 32 + (ZI)) * CH]);                      \
        float ww = (W);                                                              \
        acc.x += ww * cv.x; acc.y += ww * cv.y; acc.z += ww * cv.z; acc.w += ww * cv.w; \
    }
    CORNER(ix0, iy0, iz0, gx0 * gy0 * gz0)
    CORNER(ix0, iy0, iz1, gx0 * gy0 * fz)
    CORNER(ix0, iy1, iz0, gx0 * fy * gz0)
    CORNER(ix0, iy1, iz1, gx0 * fy * fz)
    CORNER(ix1, iy0, iz0, fx * gy0 * gz0)
    CORNER(ix1, iy0, iz1, fx * gy0 * fz)
    CORNER(ix1, iy1, iz0, fx * fy * gz0)
    CORNER(ix1, iy1, iz1, fx * fy * fz)
#undef CORNER

    size_t ob = ((size_t)b * CH + cg * 4) * NPTS + n;
    out[ob] = acc.x;
    out[ob + NPTS] = acc.y;
    out[ob + 2 * (size_t)NPTS] = acc.z;
    out[ob + 3 * (size_t)NPTS] = acc.w;
}

// ---------------- echo coords into output tail -----------------------------
__global__ void copy_coords_kernel(float* __restrict__ out, const float* __restrict__ coords) {
    int t = blockIdx.x * 256 + threadIdx.x;   // t < BATCH*3*NPTS/4 = 393216
    reinterpret_cast<float4*>(out)[t] = reinterpret_cast<const float4*>(coords)[t];
}

// ---------------- launch ----------------------------------------------------
extern "C" void kernel_launch(void* const* d_in, const int* in_sizes, int n_in,
                              void* d_out, int out_size) {
    (void)in_sizes; (void)n_in; (void)out_size;
    const float* feats  = (const float*)d_in[0];
    const float* coords = (const float*)d_in[1];
    const float* w1  = (const float*)d_in[2];
    const float* b1  = (const float*)d_in[3];
    const float* g1  = (const float*)d_in[4];
    const float* be1 = (const float*)d_in[5];
    const float* m1  = (const float*)d_in[6];
    const float* v1  = (const float*)d_in[7];
    const float* w2  = (const float*)d_in[8];
    const float* b2  = (const float*)d_in[9];
    const float* g2  = (const float*)d_in[10];
    const float* be2 = (const float*)d_in[11];
    const float* m2  = (const float*)d_in[12];
    const float* v2  = (const float*)d_in[13];
    float* out = (float*)d_out;

    float *p_g0, *p_g1, *p_g2, *p_wT1, *p_wT2, *p_be1, *p_be2;
    cudaGetSymbolAddress((void**)&p_g0, d_grid0);
    cudaGetSymbolAddress((void**)&p_g1, d_grid1);
    cudaGetSymbolAddress((void**)&p_g2, d_grid2);
    cudaGetSymbolAddress((void**)&p_wT1, d_wT1);
    cudaGetSymbolAddress((void**)&p_wT2, d_wT2);
    cudaGetSymbolAddress((void**)&p_be1, d_biasE1);
    cudaGetSymbolAddress((void**)&p_be2, d_biasE2);

    cudaFuncSetAttribute(conv_kernel, cudaFuncAttributeMaxDynamicSharedMemorySize, CONV_SMEM);

    zero_kernel<<<16640, 256>>>();
    mean_kernel<<<BATCH, 256>>>(coords);
    scale_kernel<<<BATCH, 256>>>(coords);
    prep_kernel<<<(27 * 64 * 64 + 255) / 256, 256>>>(w1, b1, g1, be1, m1, v1, p_wT1, p_be1);
    prep_kernel<<<(27 * 64 * 64 + 255) / 256, 256>>>(w2, b2, g2, be2, m2, v2, p_wT2, p_be2);
    transpose_kernel<<<dim3(NPTS / 32, CH / 32, BATCH), dim3(32, 8)>>>(feats);
    scatter_kernel<<<(BATCH * NPTS) / 256, 256>>>(coords);
    avg_kernel<<<(BATCH * NVOX * 16) / 256, 256>>>();
    conv_kernel<<<BATCH * 128, 256, CONV_SMEM>>>(p_g0, p_g1, p_wT1, p_be1);
    conv_kernel<<<BATCH * 128, 256, CONV_SMEM>>>(p_g1, p_g2, p_wT2, p_be2);
    devox_kernel<<<dim3(NPTS / 256, 16, BATCH), 256>>>(out, p_g2);
    copy_coords_kernel<<<(BATCH * 3 * NPTS / 4) / 256, 256>>>(
        out + (size_t)BATCH * CH * NPTS, coords);
}

// round 6
// speedup vs baseline: 1.7011x; 1.1273x over previous
#include <cuda_runtime.h>

#define BATCH 8
#define CH 64
#define NPTS 65536
#define RR 32
#define NVOX 32768  // 32^3

// ---------------- scratch (__device__ globals; no allocation allowed) ------
__device__ float d_mean[BATCH * 3];
__device__ float d_scale[BATCH];
__device__ float d_voxc[BATCH * 3 * NPTS];            // clipped voxel coords
__device__ float d_cnt[BATCH * NVOX];                 // per-voxel point counts
__device__ float d_featsT[(size_t)BATCH * NPTS * CH]; // point-major features
__device__ float d_grid0[(size_t)BATCH * NVOX * CH];  // NDHWC voxel grid
__device__ float d_grid1[(size_t)BATCH * NVOX * CH];  // after conv1
__device__ float d_grid2[(size_t)BATCH * NVOX * CH];  // after conv2
__device__ float d_wB1[27 * 64 * 64];                 // [tap][oc][ic] tf32-rounded, BN folded
__device__ float d_wT2[27 * 64 * 64];                 // [tap][ic][oc], BN folded (FFMA2 layer)
__device__ float d_biasE1[64];
__device__ float d_biasE2[64];

// ---------------- helpers ---------------------------------------------------
__device__ __forceinline__ unsigned long long fma2(unsigned long long a,
                                                   unsigned long long b,
                                                   unsigned long long c) {
    unsigned long long d;
    asm("fma.rn.f32x2 %0, %1, %2, %3;" : "=l"(d) : "l"(a), "l"(b), "l"(c));
    return d;
}
__device__ __forceinline__ unsigned long long bcast2(float x) {
    unsigned long long d;
    asm("mov.b64 %0, {%1, %1};" : "=l"(d) : "f"(x));
    return d;
}
__device__ __forceinline__ float2 unpack2(unsigned long long v) {
    float2 r;
    asm("mov.b64 {%0, %1}, %2;" : "=f"(r.x), "=f"(r.y) : "l"(v));
    return r;
}
__device__ __forceinline__ float to_tf32(float x) {
    float y;
    asm("cvt.rna.tf32.f32 %0, %1;" : "=f"(y) : "f"(x));
    return y;
}
__device__ __forceinline__ void mma_tf32(float& d0, float& d1, float& d2, float& d3,
                                         unsigned a0, unsigned a1, unsigned a2, unsigned a3,
                                         unsigned b0, unsigned b1) {
    asm("mma.sync.aligned.m16n8k8.row.col.f32.tf32.tf32.f32 "
        "{%0,%1,%2,%3},{%4,%5,%6,%7},{%8,%9},{%0,%1,%2,%3};"
        : "+f"(d0), "+f"(d1), "+f"(d2), "+f"(d3)
        : "r"(a0), "r"(a1), "r"(a2), "r"(a3), "r"(b0), "r"(b1));
}

// ============ launch #1: fused zero + transpose + mean/scale ================
// blocks [0,16640): zero grid0+cnt; [16640,49408): feature transpose;
// [49408,49416): per-batch mean + max-radius.
#define ZBLK 16640
#define TBLK 32768
__global__ void fused_init_kernel(const float* __restrict__ f,
                                  const float* __restrict__ coords) {
    __shared__ float tile[32][33];
    __shared__ float red[3][256];
    int blk = blockIdx.x;
    int tid = threadIdx.x;

    if (blk < ZBLK) {
        size_t t = (size_t)blk * 256 + tid;
        const size_t g4 = (size_t)BATCH * NVOX * CH / 4;
        float4 z = make_float4(0.f, 0.f, 0.f, 0.f);
        if (t < g4) {
            reinterpret_cast<float4*>(d_grid0)[t] = z;
        } else {
            size_t u = t - g4;
            if (u < (size_t)BATCH * NVOX / 4) reinterpret_cast<float4*>(d_cnt)[u] = z;
        }
        return;
    }
    if (blk < ZBLK + TBLK) {
        int tb = blk - ZBLK;
        int n0 = (tb & 2047) * 32;
        int c0 = ((tb >> 11) & 1) * 32;
        int b = tb >> 12;
        int tx = tid & 31, ty = tid >> 5;   // 32 x 8
        const float* fb = f + (size_t)b * CH * NPTS;
#pragma unroll
        for (int i = 0; i < 4; i++) {
            int c = c0 + ty + i * 8;
            tile[ty + i * 8][tx] = fb[(size_t)c * NPTS + n0 + tx];
        }
        __syncthreads();
#pragma unroll
        for (int i = 0; i < 4; i++) {
            int n = n0 + ty + i * 8;
            d_featsT[((size_t)b * NPTS + n) * CH + c0 + tx] = tile[tx][ty + i * 8];
        }
        return;
    }
    // mean + scale, one block per batch
    int b = blk - (ZBLK + TBLK);
    const float* cb = coords + (size_t)b * 3 * NPTS;
    float s0 = 0.f, s1 = 0.f, s2 = 0.f;
    for (int n = tid; n < NPTS; n += 256) {
        s0 += cb[n];
        s1 += cb[NPTS + n];
        s2 += cb[2 * NPTS + n];
    }
    red[0][tid] = s0; red[1][tid] = s1; red[2][tid] = s2;
    __syncthreads();
    for (int off = 128; off > 0; off >>= 1) {
        if (tid < off) {
            red[0][tid] += red[0][tid + off];
            red[1][tid] += red[1][tid + off];
            red[2][tid] += red[2][tid + off];
        }
        __syncthreads();
    }
    float m0 = red[0][0] / (float)NPTS;
    float m1 = red[1][0] / (float)NPTS;
    float m2 = red[2][0] / (float)NPTS;
    __syncthreads();
    float mx = 0.f;
    for (int n = tid; n < NPTS; n += 256) {
        float dx = cb[n] - m0;
        float dy = cb[NPTS + n] - m1;
        float dz = cb[2 * NPTS + n] - m2;
        mx = fmaxf(mx, dx * dx + dy * dy + dz * dz);
    }
    red[0][tid] = mx;
    __syncthreads();
    for (int off = 128; off > 0; off >>= 1) {
        if (tid < off) red[0][tid] = fmaxf(red[0][tid], red[0][tid + off]);
        __syncthreads();
    }
    if (tid == 0) {
        d_mean[b * 3 + 0] = m0;
        d_mean[b * 3 + 1] = m1;
        d_mean[b * 3 + 2] = m2;
        d_scale[b] = sqrtf(red[0][0]);
    }
}

// ============ launch #2: scatter ============================================
__global__ void scatter_kernel(const float* __restrict__ coords) {
    int t = blockIdx.x * 256 + threadIdx.x;       // [0, BATCH*NPTS)
    int b = t >> 16;
    int n = t & (NPTS - 1);
    const float* cb = coords + (size_t)b * 3 * NPTS;
    float m0 = d_mean[b * 3 + 0], m1 = d_mean[b * 3 + 1], m2 = d_mean[b * 3 + 2];
    float den = d_scale[b] * 2.0f;

    float vx = fminf(fmaxf(((cb[n]            - m0) / den + 0.5f) * 32.0f, 0.f), 31.f);
    float vy = fminf(fmaxf(((cb[NPTS + n]     - m1) / den + 0.5f) * 32.0f, 0.f), 31.f);
    float vz = fminf(fmaxf(((cb[2 * NPTS + n] - m2) / den + 0.5f) * 32.0f, 0.f), 31.f);

    float* vout = d_voxc + (size_t)b * 3 * NPTS;
    vout[n] = vx;
    vout[NPTS + n] = vy;
    vout[2 * NPTS + n] = vz;

    int ix = (int)rintf(vx);
    int iy = (int)rintf(vy);
    int iz = (int)rintf(vz);
    int idx = (ix * 32 + iy) * 32 + iz;

    atomicAdd(&d_cnt[b * NVOX + idx], 1.0f);
    float* gb = &d_grid0[((size_t)b * NVOX + idx) * CH];
    const float4* src = reinterpret_cast<const float4*>(
        d_featsT + ((size_t)b * NPTS + n) * CH);
#pragma unroll
    for (int c4 = 0; c4 < 16; c4++) {
        float4 fv = src[c4];
        asm volatile("red.global.add.v4.f32 [%0], {%1, %2, %3, %4};"
                     :: "l"(gb + c4 * 4), "f"(fv.x), "f"(fv.y), "f"(fv.z), "f"(fv.w)
                     : "memory");
    }
}

// ============ launch #3: fused avg + prep1(tf32) + prep2(FFMA2) =============
// blocks [0,16384): avg; [16384,16816): prep layer1; [16816,17248): prep layer2
#define ABLK 16384
#define PBLK 432
__global__ void fused_mid_kernel(const float* __restrict__ w1, const float* __restrict__ b1,
                                 const float* __restrict__ g1, const float* __restrict__ be1,
                                 const float* __restrict__ m1, const float* __restrict__ v1,
                                 const float* __restrict__ w2, const float* __restrict__ b2,
                                 const float* __restrict__ g2, const float* __restrict__ be2,
                                 const float* __restrict__ m2, const float* __restrict__ v2) {
    int blk = blockIdx.x, tid = threadIdx.x;
    if (blk < ABLK) {
        int t = blk * 256 + tid;
        int vox = t >> 4;
        int c4 = t & 15;
        float inv = 1.0f / fmaxf(d_cnt[vox], 1.0f);
        float4* p = reinterpret_cast<float4*>(&d_grid0[(size_t)vox * CH + c4 * 4]);
        float4 x = *p;
        x.x *= inv; x.y *= inv; x.z *= inv; x.w *= inv;
        *p = x;
        return;
    }
    if (blk < ABLK + PBLK) {
        // layer 1: [tap][oc][ic], tf32-rounded, BN-scale folded
        int i = (blk - ABLK) * 256 + tid;
        if (i < 64) {
            float sc = g1[i] * rsqrtf(v1[i] + 1e-4f);
            d_biasE1[i] = (b1[i] - m1[i]) * sc + be1[i];
        }
        if (i < 27 * 64 * 64) {
            int ic = i & 63;
            int oc = (i >> 6) & 63;
            int tap = i >> 12;
            float sc = g1[oc] * rsqrtf(v1[oc] + 1e-4f);
            d_wB1[i] = to_tf32(w1[(oc * 64 + ic) * 27 + tap] * sc);
        }
        return;
    }
    {
        // layer 2: [tap][ic][oc] for FFMA2 conv
        int i = (blk - ABLK - PBLK) * 256 + tid;
        if (i < 64) {
            float sc = g2[i] * rsqrtf(v2[i] + 1e-4f);
            d_biasE2[i] = (b2[i] - m2[i]) * sc + be2[i];
        }
        if (i < 27 * 64 * 64) {
            int oc = i & 63;
            int ic = (i >> 6) & 63;
            int tap = i >> 12;
            float sc = g2[oc] * rsqrtf(v2[oc] + 1e-4f);
            d_wT2[i] = w2[(oc * 64 + ic) * 27 + tap] * sc;
        }
        return;
    }
}

// ============ launch #4: conv1 — HMMA tf32, 2-pass A-split ==================
// Tile 4x4x8 = 128 vox, 8 warps x m16. Halo 6x6x10 rows, stride 68 (fp32).
// Weights staged per tap as [oc][ic] stride 76 (conflict-free B-frag LDS).
#define H1VOX 360
#define ISTR 68
#define WSTR 76
#define C1_IN (H1VOX * ISTR)            // 24480 floats
#define C1_W (64 * WSTR)                // 4864 floats
#define C1_SMEM ((C1_IN + C1_W) * 4)    // ~117.4 KB

__global__ void __launch_bounds__(256, 1) conv1_kernel(const float* __restrict__ gin,
                                                       float* __restrict__ gout,
                                                       const float* __restrict__ wB,
                                                       const float* __restrict__ biasE) {
    extern __shared__ float sh[];
    float* in_sh = sh;
    float* w_sh = sh + C1_IN;
    int tid = threadIdx.x;
    int bx = blockIdx.x;
    int b = bx >> 8;              // 256 tiles/batch
    int tile = bx & 255;
    int x0 = (tile >> 5) * 4;
    int y0 = ((tile >> 2) & 7) * 4;
    int z0 = (tile & 3) * 8;

    // halo load: 6x6x10 rows x 64ch fp32, zero-padded
    for (int s = tid; s < H1VOX * 16; s += 256) {
        int vox = s >> 4, c4 = s & 15;
        int hz = vox % 10;
        int tmp = vox / 10;
        int hy = tmp % 6;
        int hx = tmp / 6;
        int gx = x0 + hx - 1, gy = y0 + hy - 1, gz = z0 + hz - 1;
        float4 val = make_float4(0.f, 0.f, 0.f, 0.f);
        if ((unsigned)gx < 32u && (unsigned)gy < 32u && (unsigned)gz < 32u)
            val = *reinterpret_cast<const float4*>(
                &gin[((((size_t)b * 32 + gx) * 32 + gy) * 32 + gz) * CH + c4 * 4]);
        *reinterpret_cast<float4*>(&in_sh[vox * ISTR + c4 * 4]) = val;
    }

    int w = tid >> 5;             // warp id
    int lane = tid & 31;
    int xl = w >> 1;              // local x in [0,4)
    int ybase = (w & 1) * 2;      // local y for m-rows 0..7 (rows 8..15 -> +1)
    int zq = lane >> 2;           // z = lane/4
    int kq = lane & 3;            // col-in-quad

    float acc[8][4];
#pragma unroll
    for (int nb = 0; nb < 8; nb++)
#pragma unroll
        for (int j = 0; j < 4; j++) acc[nb][j] = 0.f;

    int bbase = (lane >> 2) * WSTR + kq;   // B-frag base offset

    for (int tap = 0; tap < 27; tap++) {
        __syncthreads();
        {   // stage weights [64 oc][64 ic] -> w_sh stride 76
            const float4* wsrc = reinterpret_cast<const float4*>(wB + tap * 4096);
            for (int i = tid; i < 1024; i += 256) {
                float4 v = wsrc[i];
                int oc = i >> 4, c = (i & 15) * 4;
                *reinterpret_cast<float4*>(&w_sh[oc * WSTR + c]) = v;
            }
        }
        __syncthreads();
        int dxi = tap / 9;
        int rr = tap - dxi * 9;
        int dyi = rr / 3;
        int dzi = rr - dyi * 3;
        int row0 = ((xl + dxi) * 6 + (ybase + dyi)) * 10 + dzi + zq;
        int addrA0 = row0 * ISTR + kq;
        int addrA1 = addrA0 + 10 * ISTR;   // y+1

#pragma unroll
        for (int kk = 0; kk < 8; kk++) {
            int k0 = kk * 8;
            float a0f = in_sh[addrA0 + k0];
            float a1f = in_sh[addrA1 + k0];
            float a2f = in_sh[addrA0 + k0 + 4];
            float a3f = in_sh[addrA1 + k0 + 4];
            float h0 = to_tf32(a0f), h1 = to_tf32(a1f), h2 = to_tf32(a2f), h3 = to_tf32(a3f);
            unsigned uh0 = __float_as_uint(h0), uh1 = __float_as_uint(h1);
            unsigned uh2 = __float_as_uint(h2), uh3 = __float_as_uint(h3);
            unsigned ul0 = __float_as_uint(a0f - h0), ul1 = __float_as_uint(a1f - h1);
            unsigned ul2 = __float_as_uint(a2f - h2), ul3 = __float_as_uint(a3f - h3);
#pragma unroll
            for (int nb = 0; nb < 8; nb++) {
                int wa = nb * (8 * WSTR) + k0 + bbase;
                unsigned B0 = __float_as_uint(w_sh[wa]);
                unsigned B1 = __float_as_uint(w_sh[wa + 4]);
                mma_tf32(acc[nb][0], acc[nb][1], acc[nb][2], acc[nb][3],
                         uh0, uh1, uh2, uh3, B0, B1);
                mma_tf32(acc[nb][0], acc[nb][1], acc[nb][2], acc[nb][3],
                         ul0, ul1, ul2, ul3, B0, B1);
            }
        }
    }

    // epilogue: bias + leaky, write two voxel rows (y, y+1) per thread
    int X = x0 + xl;
    int Ylo = y0 + ybase;
    int Z = z0 + zq;
    size_t base_lo = ((((size_t)b * 32 + X) * 32 + Ylo) * 32 + Z) * CH;
    size_t base_hi = base_lo + 32 * CH;   // y+1
#pragma unroll
    for (int nb = 0; nb < 8; nb++) {
        int oc = nb * 8 + 2 * kq;
        float2 bb = *reinterpret_cast<const float2*>(&biasE[oc]);
        float y00 = acc[nb][0] + bb.x;
        float y01 = acc[nb][1] + bb.y;
        float y10 = acc[nb][2] + bb.x;
        float y11 = acc[nb][3] + bb.y;
        y00 = (y00 >= 0.f) ? y00 : 0.1f * y00;
        y01 = (y01 >= 0.f) ? y01 : 0.1f * y01;
        y10 = (y10 >= 0.f) ? y10 : 0.1f * y10;
        y11 = (y11 >= 0.f) ? y11 : 0.1f * y11;
        *reinterpret_cast<float2*>(&gout[base_lo + oc]) = make_float2(y00, y01);
        *reinterpret_cast<float2*>(&gout[base_hi + oc]) = make_float2(y10, y11);
    }
}

// ============ launch #5: conv2 — FFMA2 (unchanged from R5) ==================
#define HVOX 600
#define INSTRIDE 68
#define IN_SH_FLOATS (HVOX * INSTRIDE)
#define W_SH_FLOATS (64 * 64)
#define CONV_SMEM ((IN_SH_FLOATS + W_SH_FLOATS) * 4)

__global__ void __launch_bounds__(256, 1) conv2_kernel(const float* __restrict__ gin,
                                                       float* __restrict__ gout,
                                                       const float* __restrict__ wT,
                                                       const float* __restrict__ biasE) {
    extern __shared__ float sh[];
    float* in_sh = sh;
    float* w_sh = sh + IN_SH_FLOATS;
    int tid = threadIdx.x;
    int bx = blockIdx.x;
    int b = bx >> 7;
    int tile = bx & 127;
    int tz = tile & 3;
    int ty = (tile >> 2) & 3;
    int txi = tile >> 4;
    int x0 = txi * 4, y0 = ty * 8, z0 = tz * 8;

    for (int s = tid; s < HVOX * 16; s += 256) {
        int vox = s >> 4, c4 = s & 15;
        int hx = vox / 100;
        int r = vox - hx * 100;
        int hy = r / 10;
        int hz = r - hy * 10;
        int gx = x0 + hx - 1, gy = y0 + hy - 1, gz = z0 + hz - 1;
        float4 val = make_float4(0.f, 0.f, 0.f, 0.f);
        if ((unsigned)gx < 32u && (unsigned)gy < 32u && (unsigned)gz < 32u)
            val = *reinterpret_cast<const float4*>(
                &gin[((((size_t)b * 32 + gx) * 32 + gy) * 32 + gz) * CH + c4 * 4]);
        *reinterpret_cast<float4*>(&in_sh[vox * INSTRIDE + c4 * 4]) = val;
    }

    int og = tid >> 5;
    int lane = tid & 31;
    int ly = lane >> 3;
    int lz = lane & 7;
    int oc0 = og * 8;

    unsigned long long acc2[8][4];
#pragma unroll
    for (int v = 0; v < 8; v++)
#pragma unroll
        for (int p = 0; p < 4; p++) acc2[v][p] = 0ull;

    const int voff[8] = {0, 40 * INSTRIDE, 100 * INSTRIDE, 140 * INSTRIDE,
                         200 * INSTRIDE, 240 * INSTRIDE, 300 * INSTRIDE, 340 * INSTRIDE};

    for (int tap = 0; tap < 27; tap++) {
        __syncthreads();
        {
            const float4* wsrc = reinterpret_cast<const float4*>(wT + tap * 4096);
            float4* wdst = reinterpret_cast<float4*>(w_sh);
            for (int i = tid; i < 1024; i += 256) wdst[i] = wsrc[i];
        }
        __syncthreads();
        int dxi = tap / 9;
        int rr = tap - dxi * 9;
        int dyi = rr / 3;
        int dzi = rr - dyi * 3;
        const float* ip = &in_sh[((dxi * 10 + (ly + dyi)) * 10 + (lz + dzi)) * INSTRIDE];
#pragma unroll 4
        for (int ic4 = 0; ic4 < 16; ic4++) {
            float4 a[8];
#pragma unroll
            for (int v = 0; v < 8; v++)
                a[v] = *reinterpret_cast<const float4*>(&ip[voff[v] + ic4 * 4]);
#pragma unroll
            for (int j = 0; j < 4; j++) {
                const ulonglong2* wp = reinterpret_cast<const ulonglong2*>(
                    &w_sh[((ic4 * 4 + j) << 6) + oc0]);
                ulonglong2 wA = wp[0];
                ulonglong2 wB = wp[1];
#pragma unroll
                for (int v = 0; v < 8; v++) {
                    float av = (j == 0) ? a[v].x : (j == 1) ? a[v].y
                             : (j == 2) ? a[v].z : a[v].w;
                    unsigned long long a2 = bcast2(av);
                    acc2[v][0] = fma2(a2, wA.x, acc2[v][0]);
                    acc2[v][1] = fma2(a2, wA.y, acc2[v][1]);
                    acc2[v][2] = fma2(a2, wB.x, acc2[v][2]);
                    acc2[v][3] = fma2(a2, wB.y, acc2[v][3]);
                }
            }
        }
    }

    float4 bb0 = *reinterpret_cast<const float4*>(&biasE[oc0]);
    float4 bb1 = *reinterpret_cast<const float4*>(&biasE[oc0 + 4]);
#pragma unroll
    for (int v = 0; v < 8; v++) {
        int vx = v >> 1, yh = v & 1;
        float2 p0 = unpack2(acc2[v][0]);
        float2 p1 = unpack2(acc2[v][1]);
        float2 p2 = unpack2(acc2[v][2]);
        float2 p3 = unpack2(acc2[v][3]);
        float y[8] = {p0.x + bb0.x, p0.y + bb0.y, p1.x + bb0.z, p1.y + bb0.w,
                      p2.x + bb1.x, p2.y + bb1.y, p3.x + bb1.z, p3.y + bb1.w};
#pragma unroll
        for (int k = 0; k < 8; k++) y[k] = (y[k] >= 0.f) ? y[k] : 0.1f * y[k];
        size_t o = ((((size_t)b * 32 + (x0 + vx)) * 32 + (y0 + ly + 4 * yh)) * 32
                    + (z0 + lz)) * CH + oc0;
        *reinterpret_cast<float4*>(&gout[o]) = make_float4(y[0], y[1], y[2], y[3]);
        *reinterpret_cast<float4*>(&gout[o + 4]) = make_float4(y[4], y[5], y[6], y[7]);
    }
}

// ============ launch #6: trilinear devoxelize ===============================
__global__ void devox_kernel(float* __restrict__ out, const float* __restrict__ grid) {
    int n = blockIdx.x * 256 + threadIdx.x;
    int cg = blockIdx.y;
    int b = blockIdx.z;
    const float* vc = d_voxc + (size_t)b * 3 * NPTS;
    float cx = vc[n], cy = vc[NPTS + n], cz = vc[2 * NPTS + n];
    int ix0 = (int)floorf(cx), iy0 = (int)floorf(cy), iz0 = (int)floorf(cz);
    float fx = cx - (float)ix0, fy = cy - (float)iy0, fz = cz - (float)iz0;
    int ix1 = min(ix0 + 1, 31), iy1 = min(iy0 + 1, 31), iz1 = min(iz0 + 1, 31);
    float gx0 = 1.f - fx, gy0 = 1.f - fy, gz0 = 1.f - fz;

    const float* g = grid + ((size_t)b * NVOX) * CH + cg * 4;
    float4 acc = make_float4(0.f, 0.f, 0.f, 0.f);

#define CORNER(XI, YI, ZI, W)                                                        \
    {                                                                                \
        float4 cv = *reinterpret_cast<const float4*>(                                \
            &g[(size_t)(((XI) * 32 + (YI)) * 32 + (ZI)) * CH]);                      \
        float ww = (W);                                                              \
        acc.x += ww * cv.x; acc.y += ww * cv.y; acc.z += ww * cv.z; acc.w += ww * cv.w; \
    }
    CORNER(ix0, iy0, iz0, gx0 * gy0 * gz0)
    CORNER(ix0, iy0, iz1, gx0 * gy0 * fz)
    CORNER(ix0, iy1, iz0, gx0 * fy * gz0)
    CORNER(ix0, iy1, iz1, gx0 * fy * fz)
    CORNER(ix1, iy0, iz0, fx * gy0 * gz0)
    CORNER(ix1, iy0, iz1, fx * gy0 * fz)
    CORNER(ix1, iy1, iz0, fx * fy * gz0)
    CORNER(ix1, iy1, iz1, fx * fy * fz)
#undef CORNER

    size_t ob = ((size_t)b * CH + cg * 4) * NPTS + n;
    out[ob] = acc.x;
    out[ob + NPTS] = acc.y;
    out[ob + 2 * (size_t)NPTS] = acc.z;
    out[ob + 3 * (size_t)NPTS] = acc.w;
}

// ============ launch #7: echo coords ========================================
__global__ void copy_coords_kernel(float* __restrict__ out, const float* __restrict__ coords) {
    int t = blockIdx.x * 256 + threadIdx.x;
    reinterpret_cast<float4*>(out)[t] = reinterpret_cast<const float4*>(coords)[t];
}

// ---------------- launch ----------------------------------------------------
extern "C" void kernel_launch(void* const* d_in, const int* in_sizes, int n_in,
                              void* d_out, int out_size) {
    (void)in_sizes; (void)n_in; (void)out_size;
    const float* feats  = (const float*)d_in[0];
    const float* coords = (const float*)d_in[1];
    const float* w1  = (const float*)d_in[2];
    const float* b1  = (const float*)d_in[3];
    const float* g1  = (const float*)d_in[4];
    const float* be1 = (const float*)d_in[5];
    const float* m1  = (const float*)d_in[6];
    const float* v1  = (const float*)d_in[7];
    const float* w2  = (const float*)d_in[8];
    const float* b2  = (const float*)d_in[9];
    const float* g2  = (const float*)d_in[10];
    const float* be2 = (const float*)d_in[11];
    const float* m2  = (const float*)d_in[12];
    const float* v2  = (const float*)d_in[13];
    float* out = (float*)d_out;

    float *p_g0, *p_g1, *p_g2, *p_wB1, *p_wT2, *p_be1, *p_be2;
    cudaGetSymbolAddress((void**)&p_g0, d_grid0);
    cudaGetSymbolAddress((void**)&p_g1, d_grid1);
    cudaGetSymbolAddress((void**)&p_g2, d_grid2);
    cudaGetSymbolAddress((void**)&p_wB1, d_wB1);
    cudaGetSymbolAddress((void**)&p_wT2, d_wT2);
    cudaGetSymbolAddress((void**)&p_be1, d_biasE1);
    cudaGetSymbolAddress((void**)&p_be2, d_biasE2);

    cudaFuncSetAttribute(conv1_kernel, cudaFuncAttributeMaxDynamicSharedMemorySize, C1_SMEM);
    cudaFuncSetAttribute(conv2_kernel, cudaFuncAttributeMaxDynamicSharedMemorySize, CONV_SMEM);

    fused_init_kernel<<<ZBLK + TBLK + BATCH, 256>>>(feats, coords);          // 1
    scatter_kernel<<<(BATCH * NPTS) / 256, 256>>>(coords);                    // 2
    fused_mid_kernel<<<ABLK + 2 * PBLK, 256>>>(w1, b1, g1, be1, m1, v1,       // 3
                                               w2, b2, g2, be2, m2, v2);
    conv1_kernel<<<BATCH * 256, 256, C1_SMEM>>>(p_g0, p_g1, p_wB1, p_be1);    // 4 (ncu slot)
    conv2_kernel<<<BATCH * 128, 256, CONV_SMEM>>>(p_g1, p_g2, p_wT2, p_be2);  // 5 (ncu slot)
    devox_kernel<<<dim3(NPTS / 256, 16, BATCH), 256>>>(out, p_g2);            // 6
    copy_coords_kernel<<<(BATCH * 3 * NPTS / 4) / 256, 256>>>(                // 7
        out + (size_t)BATCH * CH * NPTS, coords);
}

// round 7
// speedup vs baseline: 3.4175x; 2.0090x over previous
#include <cuda_runtime.h>
#include <cstdint>

#define BATCH 8
#define CH 64
#define NPTS 65536
#define RR 32
#define NVOX 32768  // 32^3

// ---------------- scratch (__device__ globals; no allocation allowed) ------
__device__ float d_mean[BATCH * 3];
__device__ float d_scale[BATCH];
__device__ float d_voxc[BATCH * 3 * NPTS];            // clipped voxel coords
__device__ float d_cnt[BATCH * NVOX];                 // per-voxel point counts
__device__ float d_featsT[(size_t)BATCH * NPTS * CH]; // point-major features
__device__ float d_grid0[(size_t)BATCH * NVOX * CH];  // NDHWC voxel grid
__device__ float d_grid1[(size_t)BATCH * NVOX * CH];  // after conv1
__device__ float d_grid2[(size_t)BATCH * NVOX * CH];  // after conv2
__device__ float d_wB1[27 * 64 * 64];                 // [tap][oc][ic] tf32(RNA), BN folded
__device__ float d_wB2[27 * 64 * 64];                 // [tap][oc][ic] tf32(RNA), BN folded
__device__ float d_biasE1[64];
__device__ float d_biasE2[64];

// ---------------- helpers ---------------------------------------------------
__device__ __forceinline__ float to_tf32(float x) {
    float y;
    asm("cvt.rna.tf32.f32 %0, %1;" : "=f"(y) : "f"(x));
    return y;
}
__device__ __forceinline__ void mma_tf32(float& d0, float& d1, float& d2, float& d3,
                                         unsigned a0, unsigned a1, unsigned a2, unsigned a3,
                                         unsigned b0, unsigned b1) {
    asm("mma.sync.aligned.m16n8k8.row.col.f32.tf32.tf32.f32 "
        "{%0,%1,%2,%3},{%4,%5,%6,%7},{%8,%9},{%0,%1,%2,%3};"
        : "+f"(d0), "+f"(d1), "+f"(d2), "+f"(d3)
        : "r"(a0), "r"(a1), "r"(a2), "r"(a3), "r"(b0), "r"(b1));
}

// ============ launch #1: fused zero + transpose + mean/scale ================
#define ZBLK 16640
#define TBLK 32768
__global__ void fused_init_kernel(const float* __restrict__ f,
                                  const float* __restrict__ coords) {
    __shared__ float tile[32][33];
    __shared__ float red[3][256];
    int blk = blockIdx.x;
    int tid = threadIdx.x;

    if (blk < ZBLK) {
        size_t t = (size_t)blk * 256 + tid;
        const size_t g4 = (size_t)BATCH * NVOX * CH / 4;
        float4 z = make_float4(0.f, 0.f, 0.f, 0.f);
        if (t < g4) {
            reinterpret_cast<float4*>(d_grid0)[t] = z;
        } else {
            size_t u = t - g4;
            if (u < (size_t)BATCH * NVOX / 4) reinterpret_cast<float4*>(d_cnt)[u] = z;
        }
        return;
    }
    if (blk < ZBLK + TBLK) {
        int tb = blk - ZBLK;
        int n0 = (tb & 2047) * 32;
        int c0 = ((tb >> 11) & 1) * 32;
        int b = tb >> 12;
        int tx = tid & 31, ty = tid >> 5;   // 32 x 8
        const float* fb = f + (size_t)b * CH * NPTS;
#pragma unroll
        for (int i = 0; i < 4; i++) {
            int c = c0 + ty + i * 8;
            tile[ty + i * 8][tx] = fb[(size_t)c * NPTS + n0 + tx];
        }
        __syncthreads();
#pragma unroll
        for (int i = 0; i < 4; i++) {
            int n = n0 + ty + i * 8;
            d_featsT[((size_t)b * NPTS + n) * CH + c0 + tx] = tile[tx][ty + i * 8];
        }
        return;
    }
    // mean + scale, one block per batch
    int b = blk - (ZBLK + TBLK);
    const float* cb = coords + (size_t)b * 3 * NPTS;
    float s0 = 0.f, s1 = 0.f, s2 = 0.f;
    for (int n = tid; n < NPTS; n += 256) {
        s0 += cb[n];
        s1 += cb[NPTS + n];
        s2 += cb[2 * NPTS + n];
    }
    red[0][tid] = s0; red[1][tid] = s1; red[2][tid] = s2;
    __syncthreads();
    for (int off = 128; off > 0; off >>= 1) {
        if (tid < off) {
            red[0][tid] += red[0][tid + off];
            red[1][tid] += red[1][tid + off];
            red[2][tid] += red[2][tid + off];
        }
        __syncthreads();
    }
    float m0 = red[0][0] / (float)NPTS;
    float m1 = red[1][0] / (float)NPTS;
    float m2 = red[2][0] / (float)NPTS;
    __syncthreads();
    float mx = 0.f;
    for (int n = tid; n < NPTS; n += 256) {
        float dx = cb[n] - m0;
        float dy = cb[NPTS + n] - m1;
        float dz = cb[2 * NPTS + n] - m2;
        mx = fmaxf(mx, dx * dx + dy * dy + dz * dz);
    }
    red[0][tid] = mx;
    __syncthreads();
    for (int off = 128; off > 0; off >>= 1) {
        if (tid < off) red[0][tid] = fmaxf(red[0][tid], red[0][tid + off]);
        __syncthreads();
    }
    if (tid == 0) {
        d_mean[b * 3 + 0] = m0;
        d_mean[b * 3 + 1] = m1;
        d_mean[b * 3 + 2] = m2;
        d_scale[b] = sqrtf(red[0][0]);
    }
}

// ============ launch #2: scatter ============================================
__global__ void scatter_kernel(const float* __restrict__ coords) {
    int t = blockIdx.x * 256 + threadIdx.x;       // [0, BATCH*NPTS)
    int b = t >> 16;
    int n = t & (NPTS - 1);
    const float* cb = coords + (size_t)b * 3 * NPTS;
    float m0 = d_mean[b * 3 + 0], m1 = d_mean[b * 3 + 1], m2 = d_mean[b * 3 + 2];
    float den = d_scale[b] * 2.0f;

    float vx = fminf(fmaxf(((cb[n]            - m0) / den + 0.5f) * 32.0f, 0.f), 31.f);
    float vy = fminf(fmaxf(((cb[NPTS + n]     - m1) / den + 0.5f) * 32.0f, 0.f), 31.f);
    float vz = fminf(fmaxf(((cb[2 * NPTS + n] - m2) / den + 0.5f) * 32.0f, 0.f), 31.f);

    float* vout = d_voxc + (size_t)b * 3 * NPTS;
    vout[n] = vx;
    vout[NPTS + n] = vy;
    vout[2 * NPTS + n] = vz;

    int ix = (int)rintf(vx);
    int iy = (int)rintf(vy);
    int iz = (int)rintf(vz);
    int idx = (ix * 32 + iy) * 32 + iz;

    atomicAdd(&d_cnt[b * NVOX + idx], 1.0f);
    float* gb = &d_grid0[((size_t)b * NVOX + idx) * CH];
    const float4* src = reinterpret_cast<const float4*>(
        d_featsT + ((size_t)b * NPTS + n) * CH);
#pragma unroll
    for (int c4 = 0; c4 < 16; c4++) {
        float4 fv = src[c4];
        asm volatile("red.global.add.v4.f32 [%0], {%1, %2, %3, %4};"
                     :: "l"(gb + c4 * 4), "f"(fv.x), "f"(fv.y), "f"(fv.z), "f"(fv.w)
                     : "memory");
    }
}

// ============ launch #3: fused avg + prep1 + prep2 (both tf32) ==============
#define ABLK 16384
#define PBLK 432
__global__ void fused_mid_kernel(const float* __restrict__ w1, const float* __restrict__ b1,
                                 const float* __restrict__ g1, const float* __restrict__ be1,
                                 const float* __restrict__ m1, const float* __restrict__ v1,
                                 const float* __restrict__ w2, const float* __restrict__ b2,
                                 const float* __restrict__ g2, const float* __restrict__ be2,
                                 const float* __restrict__ m2, const float* __restrict__ v2) {
    int blk = blockIdx.x, tid = threadIdx.x;
    if (blk < ABLK) {
        int t = blk * 256 + tid;
        int vox = t >> 4;
        int c4 = t & 15;
        float inv = 1.0f / fmaxf(d_cnt[vox], 1.0f);
        float4* p = reinterpret_cast<float4*>(&d_grid0[(size_t)vox * CH + c4 * 4]);
        float4 x = *p;
        x.x *= inv; x.y *= inv; x.z *= inv; x.w *= inv;
        *p = x;
        return;
    }
    if (blk < ABLK + PBLK) {
        int i = (blk - ABLK) * 256 + tid;
        if (i < 64) {
            float sc = g1[i] * rsqrtf(v1[i] + 1e-4f);
            d_biasE1[i] = (b1[i] - m1[i]) * sc + be1[i];
        }
        if (i < 27 * 64 * 64) {
            int ic = i & 63;
            int oc = (i >> 6) & 63;
            int tap = i >> 12;
            float sc = g1[oc] * rsqrtf(v1[oc] + 1e-4f);
            d_wB1[i] = to_tf32(w1[(oc * 64 + ic) * 27 + tap] * sc);
        }
        return;
    }
    {
        int i = (blk - ABLK - PBLK) * 256 + tid;
        if (i < 64) {
            float sc = g2[i] * rsqrtf(v2[i] + 1e-4f);
            d_biasE2[i] = (b2[i] - m2[i]) * sc + be2[i];
        }
        if (i < 27 * 64 * 64) {
            int ic = i & 63;
            int oc = (i >> 6) & 63;
            int tap = i >> 12;
            float sc = g2[oc] * rsqrtf(v2[oc] + 1e-4f);
            d_wB2[i] = to_tf32(w2[(oc * 64 + ic) * 27 + tap] * sc);
        }
        return;
    }
}

// ============ launches #4/#5: conv — single-pass tf32 HMMA, cp.async ========
// Tile 4x8x8 = 256 vox, 512 threads (16 warps), each warp one m16 tile x 64 oc.
// Halo 6x10x10 rows x 64ch fp32, stride 68 (A-frag LDS conflict-free).
// Weights double-buffered [oc][ic] stride 76 (B-frag LDS conflict-free),
// staged per-tap via cp.async overlapped with compute.
#define C_HROWS 600
#define C_ISTR 68
#define C_WSTR 76
#define C_IN (C_HROWS * C_ISTR)          // 40800 floats
#define C_WBUF (64 * C_WSTR)             // 4864 floats per buffer
#define C_SMEM ((C_IN + 2 * C_WBUF) * 4) // 202112 bytes

__device__ __forceinline__ void stage_weights(const float* __restrict__ wB, int tap,
                                              uint32_t dst_base, int tid) {
    const float4* src = reinterpret_cast<const float4*>(wB + tap * 4096);
#pragma unroll
    for (int i = 0; i < 2; i++) {
        int idx = tid + i * 512;              // [0,1024)
        int oc = idx >> 4, c = (idx & 15) * 4;
        uint32_t d = dst_base + (uint32_t)(oc * C_WSTR + c) * 4u;
        asm volatile("cp.async.cg.shared.global [%0], [%1], 16;"
                     :: "r"(d), "l"(src + idx) : "memory");
    }
}

__global__ void __launch_bounds__(512, 1) conv_tc_kernel(const float* __restrict__ gin,
                                                         float* __restrict__ gout,
                                                         const float* __restrict__ wB,
                                                         const float* __restrict__ biasE) {
    extern __shared__ float sh[];
    float* in_sh = sh;
    float* w_sh = sh + C_IN;                 // 2 buffers of C_WBUF
    uint32_t wsh_u32 = (uint32_t)__cvta_generic_to_shared(w_sh);

    int tid = threadIdx.x;
    int bx = blockIdx.x;
    int b = bx >> 7;                         // 128 tiles/batch
    int tile = bx & 127;
    int x0 = (tile >> 4) * 4;                // 8 x-tiles of 4
    int y0 = ((tile >> 2) & 3) * 8;          // 4 y-tiles of 8
    int z0 = (tile & 3) * 8;                 // 4 z-tiles of 8

    // prefetch tap-0 weights (overlaps halo load)
    stage_weights(wB, 0, wsh_u32, tid);
    asm volatile("cp.async.commit_group;" ::: "memory");

    // halo load: 6x10x10 rows x 64ch, zero-padded
    for (int s = tid; s < C_HROWS * 16; s += 512) {
        int vox = s >> 4, c4 = s & 15;
        int hx = vox / 100;
        int r = vox - hx * 100;
        int hy = r / 10;
        int hz = r - hy * 10;
        int gx = x0 + hx - 1, gy = y0 + hy - 1, gz = z0 + hz - 1;
        float4 val = make_float4(0.f, 0.f, 0.f, 0.f);
        if ((unsigned)gx < 32u && (unsigned)gy < 32u && (unsigned)gz < 32u)
            val = *reinterpret_cast<const float4*>(
                &gin[((((size_t)b * 32 + gx) * 32 + gy) * 32 + gz) * CH + c4 * 4]);
        *reinterpret_cast<float4*>(&in_sh[vox * C_ISTR + c4 * 4]) = val;
    }

    int w = tid >> 5;                        // warp id [0,16)
    int lane = tid & 31;
    int xl = w >> 2;                         // [0,4)
    int yb = (w & 3) * 2;                    // m-rows 0-7 -> y=yb, 8-15 -> yb+1
    int zq = lane >> 2;                      // voxel z = m-row
    int kq = lane & 3;

    float acc[8][4];
#pragma unroll
    for (int nb = 0; nb < 8; nb++)
#pragma unroll
        for (int j = 0; j < 4; j++) acc[nb][j] = 0.f;

    int bbase = (lane >> 2) * C_WSTR + kq;

    for (int tap = 0; tap < 27; tap++) {
        const float* wcur = w_sh + (tap & 1) * C_WBUF;
        if (tap < 26) {
            stage_weights(wB, tap + 1, wsh_u32 + ((tap & 1) ^ 1) * (C_WBUF * 4), tid);
            asm volatile("cp.async.commit_group;" ::: "memory");
            asm volatile("cp.async.wait_group 1;" ::: "memory");
        } else {
            asm volatile("cp.async.wait_group 0;" ::: "memory");
        }
        __syncthreads();                     // wcur ready (tap0: also fences halo)

        int dxi = tap / 9;
        int rr9 = tap - dxi * 9;
        int dyi = rr9 / 3;
        int dzi = rr9 - dyi * 3;
        int row0 = ((xl + dxi) * 10 + (yb + dyi)) * 10 + dzi + zq;
        int aA0 = row0 * C_ISTR + kq;
        int aA1 = aA0 + 10 * C_ISTR;         // y+1 (m-rows 8-15)

#pragma unroll
        for (int kk = 0; kk < 8; kk++) {
            int k0 = kk * 8;
            unsigned u0 = __float_as_uint(to_tf32(in_sh[aA0 + k0]));
            unsigned u1 = __float_as_uint(to_tf32(in_sh[aA1 + k0]));
            unsigned u2 = __float_as_uint(to_tf32(in_sh[aA0 + k0 + 4]));
            unsigned u3 = __float_as_uint(to_tf32(in_sh[aA1 + k0 + 4]));
#pragma unroll
            for (int nb = 0; nb < 8; nb++) {
                const float* wp = wcur + nb * (8 * C_WSTR) + k0 + bbase;
                unsigned B0 = __float_as_uint(wp[0]);
                unsigned B1 = __float_as_uint(wp[4]);
                mma_tf32(acc[nb][0], acc[nb][1], acc[nb][2], acc[nb][3],
                         u0, u1, u2, u3, B0, B1);
            }
        }
        __syncthreads();                     // all done with wcur before overwrite
    }

    // epilogue: bias + leaky, write voxel rows y and y+1
    int X = x0 + xl;
    int Ylo = y0 + yb;
    int Z = z0 + zq;
    size_t base_lo = ((((size_t)b * 32 + X) * 32 + Ylo) * 32 + Z) * CH;
    size_t base_hi = base_lo + 32 * CH;      // y+1
#pragma unroll
    for (int nb = 0; nb < 8; nb++) {
        int oc = nb * 8 + 2 * kq;
        float2 bb = *reinterpret_cast<const float2*>(&biasE[oc]);
        float y00 = acc[nb][0] + bb.x;
        float y01 = acc[nb][1] + bb.y;
        float y10 = acc[nb][2] + bb.x;
        float y11 = acc[nb][3] + bb.y;
        y00 = (y00 >= 0.f) ? y00 : 0.1f * y00;
        y01 = (y01 >= 0.f) ? y01 : 0.1f * y01;
        y10 = (y10 >= 0.f) ? y10 : 0.1f * y10;
        y11 = (y11 >= 0.f) ? y11 : 0.1f * y11;
        *reinterpret_cast<float2*>(&gout[base_lo + oc]) = make_float2(y00, y01);
        *reinterpret_cast<float2*>(&gout[base_hi + oc]) = make_float2(y10, y11);
    }
}

// ============ launch #6: trilinear devoxelize ===============================
__global__ void devox_kernel(float* __restrict__ out, const float* __restrict__ grid) {
    int n = blockIdx.x * 256 + threadIdx.x;
    int cg = blockIdx.y;
    int b = blockIdx.z;
    const float* vc = d_voxc + (size_t)b * 3 * NPTS;
    float cx = vc[n], cy = vc[NPTS + n], cz = vc[2 * NPTS + n];
    int ix0 = (int)floorf(cx), iy0 = (int)floorf(cy), iz0 = (int)floorf(cz);
    float fx = cx - (float)ix0, fy = cy - (float)iy0, fz = cz - (float)iz0;
    int ix1 = min(ix0 + 1, 31), iy1 = min(iy0 + 1, 31), iz1 = min(iz0 + 1, 31);
    float gx0 = 1.f - fx, gy0 = 1.f - fy, gz0 = 1.f - fz;

    const float* g = grid + ((size_t)b * NVOX) * CH + cg * 4;
    float4 acc = make_float4(0.f, 0.f, 0.f, 0.f);

#define CORNER(XI, YI, ZI, W)                                                        \
    {                                                                                \
        float4 cv = *reinterpret_cast<const float4*>(                                \
            &g[(size_t)(((XI) * 32 + (YI)) * 32 + (ZI)) * CH]);                      \
        float ww = (W);                                                              \
        acc.x += ww * cv.x; acc.y += ww * cv.y; acc.z += ww * cv.z; acc.w += ww * cv.w; \
    }
    CORNER(ix0, iy0, iz0, gx0 * gy0 * gz0)
    CORNER(ix0, iy0, iz1, gx0 * gy0 * fz)
    CORNER(ix0, iy1, iz0, gx0 * fy * gz0)
    CORNER(ix0, iy1, iz1, gx0 * fy * fz)
    CORNER(ix1, iy0, iz0, fx * gy0 * gz0)
    CORNER(ix1, iy0, iz1, fx * gy0 * fz)
    CORNER(ix1, iy1, iz0, fx * fy * gz0)
    CORNER(ix1, iy1, iz1, fx * fy * fz)
#undef CORNER

    size_t ob = ((size_t)b * CH + cg * 4) * NPTS + n;
    out[ob] = acc.x;
    out[ob + NPTS] = acc.y;
    out[ob + 2 * (size_t)NPTS] = acc.z;
    out[ob + 3 * (size_t)NPTS] = acc.w;
}

// ============ launch #7: echo coords ========================================
__global__ void copy_coords_kernel(float* __restrict__ out, const float* __restrict__ coords) {
    int t = blockIdx.x * 256 + threadIdx.x;
    reinterpret_cast<float4*>(out)[t] = reinterpret_cast<const float4*>(coords)[t];
}

// ---------------- launch ----------------------------------------------------
extern "C" void kernel_launch(void* const* d_in, const int* in_sizes, int n_in,
                              void* d_out, int out_size) {
    (void)in_sizes; (void)n_in; (void)out_size;
    const float* feats  = (const float*)d_in[0];
    const float* coords = (const float*)d_in[1];
    const float* w1  = (const float*)d_in[2];
    const float* b1  = (const float*)d_in[3];
    const float* g1  = (const float*)d_in[4];
    const float* be1 = (const float*)d_in[5];
    const float* m1  = (const float*)d_in[6];
    const float* v1  = (const float*)d_in[7];
    const float* w2  = (const float*)d_in[8];
    const float* b2  = (const float*)d_in[9];
    const float* g2  = (const float*)d_in[10];
    const float* be2 = (const float*)d_in[11];
    const float* m2  = (const float*)d_in[12];
    const float* v2  = (const float*)d_in[13];
    float* out = (float*)d_out;

    float *p_g0, *p_g1, *p_g2, *p_wB1, *p_wB2, *p_be1, *p_be2;
    cudaGetSymbolAddress((void**)&p_g0, d_grid0);
    cudaGetSymbolAddress((void**)&p_g1, d_grid1);
    cudaGetSymbolAddress((void**)&p_g2, d_grid2);
    cudaGetSymbolAddress((void**)&p_wB1, d_wB1);
    cudaGetSymbolAddress((void**)&p_wB2, d_wB2);
    cudaGetSymbolAddress((void**)&p_be1, d_biasE1);
    cudaGetSymbolAddress((void**)&p_be2, d_biasE2);

    cudaFuncSetAttribute(conv_tc_kernel, cudaFuncAttributeMaxDynamicSharedMemorySize, C_SMEM);

    fused_init_kernel<<<ZBLK + TBLK + BATCH, 256>>>(feats, coords);           // 1
    scatter_kernel<<<(BATCH * NPTS) / 256, 256>>>(coords);                     // 2
    fused_mid_kernel<<<ABLK + 2 * PBLK, 256>>>(w1, b1, g1, be1, m1, v1,        // 3
                                               w2, b2, g2, be2, m2, v2);
    conv_tc_kernel<<<BATCH * 128, 512, C_SMEM>>>(p_g0, p_g1, p_wB1, p_be1);    // 4 (ncu slot)
    conv_tc_kernel<<<BATCH * 128, 512, C_SMEM>>>(p_g1, p_g2, p_wB2, p_be2);    // 5 (ncu slot)
    devox_kernel<<<dim3(NPTS / 256, 16, BATCH), 256>>>(out, p_g2);             // 6
    copy_coords_kernel<<<(BATCH * 3 * NPTS / 4) / 256, 256>>>(                 // 7
        out + (size_t)BATCH * CH * NPTS, coords);
}

// round 8
// speedup vs baseline: 3.7090x; 1.0853x over previous
#include <cuda_runtime.h>
#include <cstdint>

#define BATCH 8
#define CH 64
#define NPTS 65536
#define RR 32
#define NVOX 32768  // 32^3

// ---------------- scratch (__device__ globals; no allocation allowed) ------
__device__ float d_mean[BATCH * 3];
__device__ float d_scale[BATCH];
__device__ float d_voxc[BATCH * 3 * NPTS];            // clipped voxel coords
__device__ float d_cnt[BATCH * NVOX];                 // per-voxel point counts
__device__ float d_featsT[(size_t)BATCH * NPTS * CH]; // point-major features
__device__ float d_grid0[(size_t)BATCH * NVOX * CH];  // NDHWC voxel grid
__device__ float d_grid1[(size_t)BATCH * NVOX * CH];  // after conv1
__device__ float d_grid2[(size_t)BATCH * NVOX * CH];  // after conv2
__device__ float d_wB1[27 * 64 * 64];                 // [tap][oc][ic] tf32(RNA), BN folded
__device__ float d_wB2[27 * 64 * 64];                 // [tap][oc][ic] tf32(RNA), BN folded
__device__ float d_biasE1[64];
__device__ float d_biasE2[64];

// ---------------- helpers ---------------------------------------------------
__device__ __forceinline__ float to_tf32(float x) {
    float y;
    asm("cvt.rna.tf32.f32 %0, %1;" : "=f"(y) : "f"(x));
    return y;
}
__device__ __forceinline__ void mma_tf32(float& d0, float& d1, float& d2, float& d3,
                                         unsigned a0, unsigned a1, unsigned a2, unsigned a3,
                                         unsigned b0, unsigned b1) {
    asm("mma.sync.aligned.m16n8k8.row.col.f32.tf32.tf32.f32 "
        "{%0,%1,%2,%3},{%4,%5,%6,%7},{%8,%9},{%0,%1,%2,%3};"
        : "+f"(d0), "+f"(d1), "+f"(d2), "+f"(d3)
        : "r"(a0), "r"(a1), "r"(a2), "r"(a3), "r"(b0), "r"(b1));
}
__device__ __forceinline__ void ldsm_x4(unsigned& r0, unsigned& r1, unsigned& r2,
                                        unsigned& r3, uint32_t addr) {
    asm volatile("ldmatrix.sync.aligned.m8n8.x4.shared.b16 {%0,%1,%2,%3}, [%4];"
                 : "=r"(r0), "=r"(r1), "=r"(r2), "=r"(r3) : "r"(addr));
}

// ============ launch #1: fused zero + transpose + mean/scale ================
#define ZBLK 16640
#define TBLK 32768
__global__ void fused_init_kernel(const float* __restrict__ f,
                                  const float* __restrict__ coords) {
    __shared__ float tile[32][33];
    __shared__ float red[3][256];
    int blk = blockIdx.x;
    int tid = threadIdx.x;

    if (blk < ZBLK) {
        size_t t = (size_t)blk * 256 + tid;
        const size_t g4 = (size_t)BATCH * NVOX * CH / 4;
        float4 z = make_float4(0.f, 0.f, 0.f, 0.f);
        if (t < g4) {
            reinterpret_cast<float4*>(d_grid0)[t] = z;
        } else {
            size_t u = t - g4;
            if (u < (size_t)BATCH * NVOX / 4) reinterpret_cast<float4*>(d_cnt)[u] = z;
        }
        return;
    }
    if (blk < ZBLK + TBLK) {
        int tb = blk - ZBLK;
        int n0 = (tb & 2047) * 32;
        int c0 = ((tb >> 11) & 1) * 32;
        int b = tb >> 12;
        int tx = tid & 31, ty = tid >> 5;   // 32 x 8
        const float* fb = f + (size_t)b * CH * NPTS;
#pragma unroll
        for (int i = 0; i < 4; i++) {
            int c = c0 + ty + i * 8;
            tile[ty + i * 8][tx] = fb[(size_t)c * NPTS + n0 + tx];
        }
        __syncthreads();
#pragma unroll
        for (int i = 0; i < 4; i++) {
            int n = n0 + ty + i * 8;
            d_featsT[((size_t)b * NPTS + n) * CH + c0 + tx] = tile[tx][ty + i * 8];
        }
        return;
    }
    // mean + scale, one block per batch
    int b = blk - (ZBLK + TBLK);
    const float* cb = coords + (size_t)b * 3 * NPTS;
    float s0 = 0.f, s1 = 0.f, s2 = 0.f;
    for (int n = tid; n < NPTS; n += 256) {
        s0 += cb[n];
        s1 += cb[NPTS + n];
        s2 += cb[2 * NPTS + n];
    }
    red[0][tid] = s0; red[1][tid] = s1; red[2][tid] = s2;
    __syncthreads();
    for (int off = 128; off > 0; off >>= 1) {
        if (tid < off) {
            red[0][tid] += red[0][tid + off];
            red[1][tid] += red[1][tid + off];
            red[2][tid] += red[2][tid + off];
        }
        __syncthreads();
    }
    float m0 = red[0][0] / (float)NPTS;
    float m1 = red[1][0] / (float)NPTS;
    float m2 = red[2][0] / (float)NPTS;
    __syncthreads();
    float mx = 0.f;
    for (int n = tid; n < NPTS; n += 256) {
        float dx = cb[n] - m0;
        float dy = cb[NPTS + n] - m1;
        float dz = cb[2 * NPTS + n] - m2;
        mx = fmaxf(mx, dx * dx + dy * dy + dz * dz);
    }
    red[0][tid] = mx;
    __syncthreads();
    for (int off = 128; off > 0; off >>= 1) {
        if (tid < off) red[0][tid] = fmaxf(red[0][tid], red[0][tid + off]);
        __syncthreads();
    }
    if (tid == 0) {
        d_mean[b * 3 + 0] = m0;
        d_mean[b * 3 + 1] = m1;
        d_mean[b * 3 + 2] = m2;
        d_scale[b] = sqrtf(red[0][0]);
    }
}

// ============ launch #2: scatter ============================================
__global__ void scatter_kernel(const float* __restrict__ coords) {
    int t = blockIdx.x * 256 + threadIdx.x;       // [0, BATCH*NPTS)
    int b = t >> 16;
    int n = t & (NPTS - 1);
    const float* cb = coords + (size_t)b * 3 * NPTS;
    float m0 = d_mean[b * 3 + 0], m1 = d_mean[b * 3 + 1], m2 = d_mean[b * 3 + 2];
    float den = d_scale[b] * 2.0f;

    float vx = fminf(fmaxf(((cb[n]            - m0) / den + 0.5f) * 32.0f, 0.f), 31.f);
    float vy = fminf(fmaxf(((cb[NPTS + n]     - m1) / den + 0.5f) * 32.0f, 0.f), 31.f);
    float vz = fminf(fmaxf(((cb[2 * NPTS + n] - m2) / den + 0.5f) * 32.0f, 0.f), 31.f);

    float* vout = d_voxc + (size_t)b * 3 * NPTS;
    vout[n] = vx;
    vout[NPTS + n] = vy;
    vout[2 * NPTS + n] = vz;

    int ix = (int)rintf(vx);
    int iy = (int)rintf(vy);
    int iz = (int)rintf(vz);
    int idx = (ix * 32 + iy) * 32 + iz;

    atomicAdd(&d_cnt[b * NVOX + idx], 1.0f);
    float* gb = &d_grid0[((size_t)b * NVOX + idx) * CH];
    const float4* src = reinterpret_cast<const float4*>(
        d_featsT + ((size_t)b * NPTS + n) * CH);
#pragma unroll
    for (int c4 = 0; c4 < 16; c4++) {
        float4 fv = src[c4];
        asm volatile("red.global.add.v4.f32 [%0], {%1, %2, %3, %4};"
                     :: "l"(gb + c4 * 4), "f"(fv.x), "f"(fv.y), "f"(fv.z), "f"(fv.w)
                     : "memory");
    }
}

// ============ launch #3: fused avg + prep1 + prep2 (both tf32) ==============
#define ABLK 16384
#define PBLK 432
__global__ void fused_mid_kernel(const float* __restrict__ w1, const float* __restrict__ b1,
                                 const float* __restrict__ g1, const float* __restrict__ be1,
                                 const float* __restrict__ m1, const float* __restrict__ v1,
                                 const float* __restrict__ w2, const float* __restrict__ b2,
                                 const float* __restrict__ g2, const float* __restrict__ be2,
                                 const float* __restrict__ m2, const float* __restrict__ v2) {
    int blk = blockIdx.x, tid = threadIdx.x;
    if (blk < ABLK) {
        int t = blk * 256 + tid;
        int vox = t >> 4;
        int c4 = t & 15;
        float inv = 1.0f / fmaxf(d_cnt[vox], 1.0f);
        float4* p = reinterpret_cast<float4*>(&d_grid0[(size_t)vox * CH + c4 * 4]);
        float4 x = *p;
        x.x *= inv; x.y *= inv; x.z *= inv; x.w *= inv;
        *p = x;
        return;
    }
    if (blk < ABLK + PBLK) {
        int i = (blk - ABLK) * 256 + tid;
        if (i < 64) {
            float sc = g1[i] * rsqrtf(v1[i] + 1e-4f);
            d_biasE1[i] = (b1[i] - m1[i]) * sc + be1[i];
        }
        if (i < 27 * 64 * 64) {
            int ic = i & 63;
            int oc = (i >> 6) & 63;
            int tap = i >> 12;
            float sc = g1[oc] * rsqrtf(v1[oc] + 1e-4f);
            d_wB1[i] = to_tf32(w1[(oc * 64 + ic) * 27 + tap] * sc);
        }
        return;
    }
    {
        int i = (blk - ABLK - PBLK) * 256 + tid;
        if (i < 64) {
            float sc = g2[i] * rsqrtf(v2[i] + 1e-4f);
            d_biasE2[i] = (b2[i] - m2[i]) * sc + be2[i];
        }
        if (i < 27 * 64 * 64) {
            int ic = i & 63;
            int oc = (i >> 6) & 63;
            int tap = i >> 12;
            float sc = g2[oc] * rsqrtf(v2[oc] + 1e-4f);
            d_wB2[i] = to_tf32(w2[(oc * 64 + ic) * 27 + tap] * sc);
        }
        return;
    }
}

// ============ launches #4/#5: conv — tf32 HMMA m32n32/warp + ldmatrix =======
// Tile 4x8x8 = 256 vox, 512 threads (16 warps).
// Warp = (xl in [0,4), yh in {0,1}, och in {0,1}): m32 = voxels
// (x=xl, y=4yh..4yh+3, z=0..7) as 2 m16-tiles; n32 = oc 32*och..+31 (4 n8).
// Halo 6x10x10 rows x 64ch tf32-preconverted, stride 68 (A ldmatrix clean).
// Weights double-buffered [oc][ic] stride 76 (B ldmatrix clean), cp.async.
#define C_HROWS 600
#define C_ISTR 68
#define C_WSTR 76
#define C_IN (C_HROWS * C_ISTR)          // 40800 floats
#define C_WBUF (64 * C_WSTR)             // 4864 floats per buffer
#define C_SMEM ((C_IN + 2 * C_WBUF) * 4) // 202112 bytes

__device__ __forceinline__ void stage_weights(const float* __restrict__ wB, int tap,
                                              uint32_t dst_base, int tid) {
    const float4* src = reinterpret_cast<const float4*>(wB + tap * 4096);
#pragma unroll
    for (int i = 0; i < 2; i++) {
        int idx = tid + i * 512;              // [0,1024)
        int oc = idx >> 4, c = (idx & 15) * 4;
        uint32_t d = dst_base + (uint32_t)(oc * C_WSTR + c) * 4u;
        asm volatile("cp.async.cg.shared.global [%0], [%1], 16;"
                     :: "r"(d), "l"(src + idx) : "memory");
    }
}

__global__ void __launch_bounds__(512, 1) conv_tc_kernel(const float* __restrict__ gin,
                                                         float* __restrict__ gout,
                                                         const float* __restrict__ wB,
                                                         const float* __restrict__ biasE) {
    extern __shared__ float sh[];
    float* in_sh = sh;
    float* w_sh = sh + C_IN;                 // 2 buffers of C_WBUF
    uint32_t insh_u32 = (uint32_t)__cvta_generic_to_shared(in_sh);
    uint32_t wsh_u32 = (uint32_t)__cvta_generic_to_shared(w_sh);

    int tid = threadIdx.x;
    int bx = blockIdx.x;
    int b = bx >> 7;                         // 128 tiles/batch
    int tile = bx & 127;
    int x0 = (tile >> 4) * 4;                // 8 x-tiles of 4
    int y0 = ((tile >> 2) & 3) * 8;          // 4 y-tiles of 8
    int z0 = (tile & 3) * 8;                 // 4 z-tiles of 8

    // prefetch tap-0 weights (overlaps halo load)
    stage_weights(wB, 0, wsh_u32, tid);
    asm volatile("cp.async.commit_group;" ::: "memory");

    // halo load: 6x10x10 rows x 64ch, zero-padded, PRE-CONVERTED to tf32
    for (int s = tid; s < C_HROWS * 16; s += 512) {
        int vox = s >> 4, c4 = s & 15;
        int hx = vox / 100;
        int r = vox - hx * 100;
        int hy = r / 10;
        int hz = r - hy * 10;
        int gx = x0 + hx - 1, gy = y0 + hy - 1, gz = z0 + hz - 1;
        float4 val = make_float4(0.f, 0.f, 0.f, 0.f);
        if ((unsigned)gx < 32u && (unsigned)gy < 32u && (unsigned)gz < 32u) {
            val = *reinterpret_cast<const float4*>(
                &gin[((((size_t)b * 32 + gx) * 32 + gy) * 32 + gz) * CH + c4 * 4]);
            val.x = to_tf32(val.x); val.y = to_tf32(val.y);
            val.z = to_tf32(val.z); val.w = to_tf32(val.w);
        }
        *reinterpret_cast<float4*>(&in_sh[vox * C_ISTR + c4 * 4]) = val;
    }

    int w = tid >> 5;                        // warp id [0,16)
    int lane = tid & 31;
    int mp = w & 7;                          // m-pair id
    int och = w >> 3;                        // oc half
    int xl = mp >> 1;                        // [0,4)
    int yh = mp & 1;                         // y base = 4*yh
    int g = lane >> 3, lr = lane & 7;        // ldmatrix sub-tile / row

    // A ldmatrix lane base addresses (float idx), tap shift added later.
    // tile t: p = 2yh+t; sub-tile row voxel = (xl, y=2p+(g&1), z=lr); col k half g>>1.
    int arow0 = xl * 100 + (4 * yh + (g & 1)) * 10 + lr;
    int arow1 = xl * 100 + (4 * yh + 2 + (g & 1)) * 10 + lr;
    uint32_t A0base = insh_u32 + (uint32_t)(arow0 * C_ISTR + 4 * (g >> 1)) * 4u;
    uint32_t A1base = insh_u32 + (uint32_t)(arow1 * C_ISTR + 4 * (g >> 1)) * 4u;
    // B ldmatrix lane offsets within a weight buffer (bytes):
    // x4 covers 2 nb (g>>1) x 2 k-halves (g&1); row = oc = nb*8 + lr.
    uint32_t Bq0 = (uint32_t)(((och * 4 + (g >> 1)) * 8 + lr) * C_WSTR + 4 * (g & 1)) * 4u;
    uint32_t Bq1 = (uint32_t)(((och * 4 + 2 + (g >> 1)) * 8 + lr) * C_WSTR + 4 * (g & 1)) * 4u;

    float acc[2][4][4];
#pragma unroll
    for (int t = 0; t < 2; t++)
#pragma unroll
        for (int nb = 0; nb < 4; nb++)
#pragma unroll
            for (int j = 0; j < 4; j++) acc[t][nb][j] = 0.f;

    for (int tap = 0; tap < 27; tap++) {
        if (tap < 26) {
            stage_weights(wB, tap + 1, wsh_u32 + ((tap & 1) ^ 1) * (C_WBUF * 4), tid);
            asm volatile("cp.async.commit_group;" ::: "memory");
            asm volatile("cp.async.wait_group 1;" ::: "memory");
        } else {
            asm volatile("cp.async.wait_group 0;" ::: "memory");
        }
        __syncthreads();                     // wcur ready (tap0: also fences halo)

        int dxi = tap / 9;
        int rr9 = tap - dxi * 9;
        int dyi = rr9 / 3;
        int dzi = rr9 - dyi * 3;
        uint32_t tapoff = (uint32_t)((dxi * 100 + dyi * 10 + dzi) * C_ISTR) * 4u;
        uint32_t a0 = A0base + tapoff;
        uint32_t a1 = A1base + tapoff;
        uint32_t wb = wsh_u32 + (uint32_t)(tap & 1) * (C_WBUF * 4);

#pragma unroll
        for (int kk = 0; kk < 8; kk++) {
            unsigned A0[4], A1[4], B0[4], B1[4];
            ldsm_x4(A0[0], A0[1], A0[2], A0[3], a0 + kk * 32);
            ldsm_x4(A1[0], A1[1], A1[2], A1[3], a1 + kk * 32);
            ldsm_x4(B0[0], B0[1], B0[2], B0[3], wb + Bq0 + kk * 32);
            ldsm_x4(B1[0], B1[1], B1[2], B1[3], wb + Bq1 + kk * 32);
            mma_tf32(acc[0][0][0], acc[0][0][1], acc[0][0][2], acc[0][0][3],
                     A0[0], A0[1], A0[2], A0[3], B0[0], B0[1]);
            mma_tf32(acc[0][1][0], acc[0][1][1], acc[0][1][2], acc[0][1][3],
                     A0[0], A0[1], A0[2], A0[3], B0[2], B0[3]);
            mma_tf32(acc[0][2][0], acc[0][2][1], acc[0][2][2], acc[0][2][3],
                     A0[0], A0[1], A0[2], A0[3], B1[0], B1[1]);
            mma_tf32(acc[0][3][0], acc[0][3][1], acc[0][3][2], acc[0][3][3],
                     A0[0], A0[1], A0[2], A0[3], B1[2], B1[3]);
            mma_tf32(acc[1][0][0], acc[1][0][1], acc[1][0][2], acc[1][0][3],
                     A1[0], A1[1], A1[2], A1[3], B0[0], B0[1]);
            mma_tf32(acc[1][1][0], acc[1][1][1], acc[1][1][2], acc[1][1][3],
                     A1[0], A1[1], A1[2], A1[3], B0[2], B0[3]);
            mma_tf32(acc[1][2][0], acc[1][2][1], acc[1][2][2], acc[1][2][3],
                     A1[0], A1[1], A1[2], A1[3], B1[0], B1[1]);
            mma_tf32(acc[1][3][0], acc[1][3][1], acc[1][3][2], acc[1][3][3],
                     A1[0], A1[1], A1[2], A1[3], B1[2], B1[3]);
        }
        __syncthreads();                     // all reads of wcur done before restage
    }

    // epilogue: acc[t][nb]: c0/c1 -> (y=2p, z=zq, oc=ocb+2kq..+1); c2/c3 -> y=2p+1
    int zq = lane >> 2;
    int kq = lane & 3;
    int Z = z0 + zq;
#pragma unroll
    for (int t = 0; t < 2; t++) {
        int p = 2 * yh + t;
        int Ylo = y0 + 2 * p;
        size_t base_lo = ((((size_t)b * 32 + (x0 + xl)) * 32 + Ylo) * 32 + Z) * CH;
        size_t base_hi = base_lo + 32 * CH;  // y+1
#pragma unroll
        for (int nb = 0; nb < 4; nb++) {
            int oc = (och * 4 + nb) * 8 + 2 * kq;
            float2 bb = *reinterpret_cast<const float2*>(&biasE[oc]);
            float y00 = acc[t][nb][0] + bb.x;
            float y01 = acc[t][nb][1] + bb.y;
            float y10 = acc[t][nb][2] + bb.x;
            float y11 = acc[t][nb][3] + bb.y;
            y00 = (y00 >= 0.f) ? y00 : 0.1f * y00;
            y01 = (y01 >= 0.f) ? y01 : 0.1f * y01;
            y10 = (y10 >= 0.f) ? y10 : 0.1f * y10;
            y11 = (y11 >= 0.f) ? y11 : 0.1f * y11;
            *reinterpret_cast<float2*>(&gout[base_lo + oc]) = make_float2(y00, y01);
            *reinterpret_cast<float2*>(&gout[base_hi + oc]) = make_float2(y10, y11);
        }
    }
}

// ============ launch #6: trilinear devoxelize ===============================
__global__ void devox_kernel(float* __restrict__ out, const float* __restrict__ grid) {
    int n = blockIdx.x * 256 + threadIdx.x;
    int cg = blockIdx.y;
    int b = blockIdx.z;
    const float* vc = d_voxc + (size_t)b * 3 * NPTS;
    float cx = vc[n], cy = vc[NPTS + n], cz = vc[2 * NPTS + n];
    int ix0 = (int)floorf(cx), iy0 = (int)floorf(cy), iz0 = (int)floorf(cz);
    float fx = cx - (float)ix0, fy = cy - (float)iy0, fz = cz - (float)iz0;
    int ix1 = min(ix0 + 1, 31), iy1 = min(iy0 + 1, 31), iz1 = min(iz0 + 1, 31);
    float gx0 = 1.f - fx, gy0 = 1.f - fy, gz0 = 1.f - fz;

    const float* g = grid + ((size_t)b * NVOX) * CH + cg * 4;
    float4 acc = make_float4(0.f, 0.f, 0.f, 0.f);

#define CORNER(XI, YI, ZI, W)                                                        \
    {                                                                                \
        float4 cv = *reinterpret_cast<const float4*>(                                \
            &g[(size_t)(((XI) * 32 + (YI)) * 32 + (ZI)) * CH]);                      \
        float ww = (W);                                                              \
        acc.x += ww * cv.x; acc.y += ww * cv.y; acc.z += ww * cv.z; acc.w += ww * cv.w; \
    }
    CORNER(ix0, iy0, iz0, gx0 * gy0 * gz0)
    CORNER(ix0, iy0, iz1, gx0 * gy0 * fz)
    CORNER(ix0, iy1, iz0, gx0 * fy * gz0)
    CORNER(ix0, iy1, iz1, gx0 * fy * fz)
    CORNER(ix1, iy0, iz0, fx * gy0 * gz0)
    CORNER(ix1, iy0, iz1, fx * gy0 * fz)
    CORNER(ix1, iy1, iz0, fx * fy * gz0)
    CORNER(ix1, iy1, iz1, fx * fy * fz)
#undef CORNER

    size_t ob = ((size_t)b * CH + cg * 4) * NPTS + n;
    out[ob] = acc.x;
    out[ob + NPTS] = acc.y;
    out[ob + 2 * (size_t)NPTS] = acc.z;
    out[ob + 3 * (size_t)NPTS] = acc.w;
}

// ============ launch #7: echo coords ========================================
__global__ void copy_coords_kernel(float* __restrict__ out, const float* __restrict__ coords) {
    int t = blockIdx.x * 256 + threadIdx.x;
    reinterpret_cast<float4*>(out)[t] = reinterpret_cast<const float4*>(coords)[t];
}

// ---------------- launch ----------------------------------------------------
extern "C" void kernel_launch(void* const* d_in, const int* in_sizes, int n_in,
                              void* d_out, int out_size) {
    (void)in_sizes; (void)n_in; (void)out_size;
    const float* feats  = (const float*)d_in[0];
    const float* coords = (const float*)d_in[1];
    const float* w1  = (const float*)d_in[2];
    const float* b1  = (const float*)d_in[3];
    const float* g1  = (const float*)d_in[4];
    const float* be1 = (const float*)d_in[5];
    const float* m1  = (const float*)d_in[6];
    const float* v1  = (const float*)d_in[7];
    const float* w2  = (const float*)d_in[8];
    const float* b2  = (const float*)d_in[9];
    const float* g2  = (const float*)d_in[10];
    const float* be2 = (const float*)d_in[11];
    const float* m2  = (const float*)d_in[12];
    const float* v2  = (const float*)d_in[13];
    float* out = (float*)d_out;

    float *p_g0, *p_g1, *p_g2, *p_wB1, *p_wB2, *p_be1, *p_be2;
    cudaGetSymbolAddress((void**)&p_g0, d_grid0);
    cudaGetSymbolAddress((void**)&p_g1, d_grid1);
    cudaGetSymbolAddress((void**)&p_g2, d_grid2);
    cudaGetSymbolAddress((void**)&p_wB1, d_wB1);
    cudaGetSymbolAddress((void**)&p_wB2, d_wB2);
    cudaGetSymbolAddress((void**)&p_be1, d_biasE1);
    cudaGetSymbolAddress((void**)&p_be2, d_biasE2);

    cudaFuncSetAttribute(conv_tc_kernel, cudaFuncAttributeMaxDynamicSharedMemorySize, C_SMEM);

    fused_init_kernel<<<ZBLK + TBLK + BATCH, 256>>>(feats, coords);           // 1
    scatter_kernel<<<(BATCH * NPTS) / 256, 256>>>(coords);                     // 2
    fused_mid_kernel<<<ABLK + 2 * PBLK, 256>>>(w1, b1, g1, be1, m1, v1,        // 3
                                               w2, b2, g2, be2, m2, v2);
    conv_tc_kernel<<<BATCH * 128, 512, C_SMEM>>>(p_g0, p_g1, p_wB1, p_be1);    // 4 (ncu slot)
    conv_tc_kernel<<<BATCH * 128, 512, C_SMEM>>>(p_g1, p_g2, p_wB2, p_be2);    // 5 (ncu slot)
    devox_kernel<<<dim3(NPTS / 256, 16, BATCH), 256>>>(out, p_g2);             // 6
    copy_coords_kernel<<<(BATCH * 3 * NPTS / 4) / 256, 256>>>(                 // 7
        out + (size_t)BATCH * CH * NPTS, coords);
}

// round 9
// speedup vs baseline: 3.8969x; 1.0507x over previous
#include <cuda_runtime.h>
#include <cstdint>

#define BATCH 8
#define CH 64
#define NPTS 65536
#define RR 32
#define NVOX 32768  // 32^3

// ---------------- scratch (__device__ globals; no allocation allowed) ------
__device__ float d_mean[BATCH * 3];
__device__ float d_scale[BATCH];
__device__ float d_voxc[BATCH * 3 * NPTS];            // clipped voxel coords
__device__ int   d_idx[BATCH * NPTS];                 // per-point voxel index
__device__ float d_cnt[BATCH * NVOX];                 // per-voxel point counts
__device__ float d_grid0[(size_t)BATCH * NVOX * CH];  // scatter SUMS (not averaged)
__device__ float d_grid1[(size_t)BATCH * NVOX * CH];  // after conv1
__device__ float d_grid2[(size_t)BATCH * NVOX * CH];  // after conv2
__device__ float d_wB1[27 * 64 * 64];                 // [tap][oc][ic] tf32(RNA), BN folded
__device__ float d_wB2[27 * 64 * 64];
__device__ float d_biasE1[64];
__device__ float d_biasE2[64];

// ---------------- helpers ---------------------------------------------------
__device__ __forceinline__ float to_tf32(float x) {
    float y;
    asm("cvt.rna.tf32.f32 %0, %1;" : "=f"(y) : "f"(x));
    return y;
}
__device__ __forceinline__ void mma_tf32(float& d0, float& d1, float& d2, float& d3,
                                         unsigned a0, unsigned a1, unsigned a2, unsigned a3,
                                         unsigned b0, unsigned b1) {
    asm("mma.sync.aligned.m16n8k8.row.col.f32.tf32.tf32.f32 "
        "{%0,%1,%2,%3},{%4,%5,%6,%7},{%8,%9},{%0,%1,%2,%3};"
        : "+f"(d0), "+f"(d1), "+f"(d2), "+f"(d3)
        : "r"(a0), "r"(a1), "r"(a2), "r"(a3), "r"(b0), "r"(b1));
}
__device__ __forceinline__ void ldsm_x4(unsigned& r0, unsigned& r1, unsigned& r2,
                                        unsigned& r3, uint32_t addr) {
    asm volatile("ldmatrix.sync.aligned.m8n8.x4.shared.b16 {%0,%1,%2,%3}, [%4];"
                 : "=r"(r0), "=r"(r1), "=r"(r2), "=r"(r3) : "r"(addr));
}

// ============ launch #1: zero grid0+cnt, per-batch mean/scale ===============
#define ZBLK 16640
__global__ void fused_init_kernel(const float* __restrict__ coords) {
    __shared__ float red[3][256];
    int blk = blockIdx.x;
    int tid = threadIdx.x;

    if (blk < ZBLK) {
        size_t t = (size_t)blk * 256 + tid;
        const size_t g4 = (size_t)BATCH * NVOX * CH / 4;
        float4 z = make_float4(0.f, 0.f, 0.f, 0.f);
        if (t < g4) {
            reinterpret_cast<float4*>(d_grid0)[t] = z;
        } else {
            size_t u = t - g4;
            if (u < (size_t)BATCH * NVOX / 4) reinterpret_cast<float4*>(d_cnt)[u] = z;
        }
        return;
    }
    // mean + scale, one block per batch
    int b = blk - ZBLK;
    const float* cb = coords + (size_t)b * 3 * NPTS;
    float s0 = 0.f, s1 = 0.f, s2 = 0.f;
    for (int n = tid; n < NPTS; n += 256) {
        s0 += cb[n];
        s1 += cb[NPTS + n];
        s2 += cb[2 * NPTS + n];
    }
    red[0][tid] = s0; red[1][tid] = s1; red[2][tid] = s2;
    __syncthreads();
    for (int off = 128; off > 0; off >>= 1) {
        if (tid < off) {
            red[0][tid] += red[0][tid + off];
            red[1][tid] += red[1][tid + off];
            red[2][tid] += red[2][tid + off];
        }
        __syncthreads();
    }
    float m0 = red[0][0] / (float)NPTS;
    float m1 = red[1][0] / (float)NPTS;
    float m2 = red[2][0] / (float)NPTS;
    __syncthreads();
    float mx = 0.f;
    for (int n = tid; n < NPTS; n += 256) {
        float dx = cb[n] - m0;
        float dy = cb[NPTS + n] - m1;
        float dz = cb[2 * NPTS + n] - m2;
        mx = fmaxf(mx, dx * dx + dy * dy + dz * dz);
    }
    red[0][tid] = mx;
    __syncthreads();
    for (int off = 128; off > 0; off >>= 1) {
        if (tid < off) red[0][tid] = fmaxf(red[0][tid], red[0][tid + off]);
        __syncthreads();
    }
    if (tid == 0) {
        d_mean[b * 3 + 0] = m0;
        d_mean[b * 3 + 1] = m1;
        d_mean[b * 3 + 2] = m2;
        d_scale[b] = sqrtf(red[0][0]);
    }
}

// ============ launch #2: voxelize coords -> voxc, idx, cnt ==================
__global__ void voxelize_kernel(const float* __restrict__ coords) {
    int t = blockIdx.x * 256 + threadIdx.x;       // [0, BATCH*NPTS)
    int b = t >> 16;
    int n = t & (NPTS - 1);
    const float* cb = coords + (size_t)b * 3 * NPTS;
    float m0 = d_mean[b * 3 + 0], m1 = d_mean[b * 3 + 1], m2 = d_mean[b * 3 + 2];
    float den = d_scale[b] * 2.0f;

    float vx = fminf(fmaxf(((cb[n]            - m0) / den + 0.5f) * 32.0f, 0.f), 31.f);
    float vy = fminf(fmaxf(((cb[NPTS + n]     - m1) / den + 0.5f) * 32.0f, 0.f), 31.f);
    float vz = fminf(fmaxf(((cb[2 * NPTS + n] - m2) / den + 0.5f) * 32.0f, 0.f), 31.f);

    float* vout = d_voxc + (size_t)b * 3 * NPTS;
    vout[n] = vx;
    vout[NPTS + n] = vy;
    vout[2 * NPTS + n] = vz;

    int ix = (int)rintf(vx);   // round-half-even, matches jnp.round
    int iy = (int)rintf(vy);
    int iz = (int)rintf(vz);
    int idx = (ix * 32 + iy) * 32 + iz;
    d_idx[t] = idx;
    atomicAdd(&d_cnt[b * NVOX + idx], 1.0f);
}

// ============ launch #3: transpose-scatter feats directly into grid0 ========
// grid (NPTS/32, 2 c-halves, BATCH), block (32, 8).
__global__ void trans_scatter_kernel(const float* __restrict__ f) {
    __shared__ float tile[32][33];     // [c][n]
    int b = blockIdx.z;
    int c0 = blockIdx.y * 32;
    int n0 = blockIdx.x * 32;
    int tx = threadIdx.x, ty = threadIdx.y;
    const float* fb = f + (size_t)b * CH * NPTS;
#pragma unroll
    for (int i = 0; i < 4; i++) {
        int c = c0 + ty + i * 8;
        tile[ty + i * 8][tx] = fb[(size_t)c * NPTS + n0 + tx];
    }
    __syncthreads();
    int n = n0 + tx;
    int idx = d_idx[b * NPTS + n];
    float* gb = &d_grid0[((size_t)b * NVOX + idx) * CH + c0 + ty * 4];
    float v0 = tile[ty * 4 + 0][tx];
    float v1 = tile[ty * 4 + 1][tx];
    float v2 = tile[ty * 4 + 2][tx];
    float v3 = tile[ty * 4 + 3][tx];
    asm volatile("red.global.add.v4.f32 [%0], {%1, %2, %3, %4};"
                 :: "l"(gb), "f"(v0), "f"(v1), "f"(v2), "f"(v3) : "memory");
}

// ============ launch #4: weight prep (both layers, tf32 RNA + BN fold) ======
#define PBLK 432
__global__ void prep_kernel(const float* __restrict__ w1, const float* __restrict__ b1,
                            const float* __restrict__ g1, const float* __restrict__ be1,
                            const float* __restrict__ m1, const float* __restrict__ v1,
                            const float* __restrict__ w2, const float* __restrict__ b2,
                            const float* __restrict__ g2, const float* __restrict__ be2,
                            const float* __restrict__ m2, const float* __restrict__ v2) {
    int blk = blockIdx.x, tid = threadIdx.x;
    const float* w;  const float* bs; const float* g;  const float* be;
    const float* m;  const float* v;  float* wB; float* biasE;
    int i;
    if (blk < PBLK) {
        i = blk * 256 + tid;
        w = w1; bs = b1; g = g1; be = be1; m = m1; v = v1; wB = d_wB1; biasE = d_biasE1;
    } else {
        i = (blk - PBLK) * 256 + tid;
        w = w2; bs = b2; g = g2; be = be2; m = m2; v = v2; wB = d_wB2; biasE = d_biasE2;
    }
    if (i < 64) {
        float sc = g[i] * rsqrtf(v[i] + 1e-4f);
        biasE[i] = (bs[i] - m[i]) * sc + be[i];
    }
    if (i < 27 * 64 * 64) {
        int ic = i & 63;
        int oc = (i >> 6) & 63;
        int tap = i >> 12;
        float sc = g[oc] * rsqrtf(v[oc] + 1e-4f);
        wB[i] = to_tf32(w[(oc * 64 + ic) * 27 + tap] * sc);
    }
}

// ============ launches #5/#6: conv — tf32 HMMA, 3-stage ring, 1 bar/tap =====
// Tile 4x8x8 = 256 vox, 512 threads (16 warps), warp = m32 x n32.
// Halo 6x10x10 rows x 64ch tf32-preconverted, stride 68.
// conv1 additionally scales halo by 1/max(cnt,1) (fused averaging).
#define C_HROWS 600
#define C_ISTR 68
#define C_WSTR 76
#define C_IN (C_HROWS * C_ISTR)          // 40800 floats
#define C_WBUF (64 * C_WSTR)             // 4864 floats per stage
#define C_SMEM ((C_IN + 3 * C_WBUF) * 4) // 221568 bytes

__device__ __forceinline__ void stage_weights(const float* __restrict__ wB, int tap,
                                              uint32_t dst_base, int tid) {
    const float4* src = reinterpret_cast<const float4*>(wB + tap * 4096);
#pragma unroll
    for (int i = 0; i < 2; i++) {
        int idx = tid + i * 512;              // [0,1024)
        int oc = idx >> 4, c = (idx & 15) * 4;
        uint32_t d = dst_base + (uint32_t)(oc * C_WSTR + c) * 4u;
        asm volatile("cp.async.cg.shared.global [%0], [%1], 16;"
                     :: "r"(d), "l"(src + idx) : "memory");
    }
}

__global__ void __launch_bounds__(512, 1) conv_tc_kernel(const float* __restrict__ gin,
                                                         float* __restrict__ gout,
                                                         const float* __restrict__ wB,
                                                         const float* __restrict__ biasE,
                                                         const float* __restrict__ cnt) {
    extern __shared__ float sh[];
    float* in_sh = sh;
    float* w_sh = sh + C_IN;                 // 3 stages of C_WBUF
    uint32_t insh_u32 = (uint32_t)__cvta_generic_to_shared(in_sh);
    uint32_t wsh_u32 = (uint32_t)__cvta_generic_to_shared(w_sh);

    int tid = threadIdx.x;
    int bx = blockIdx.x;
    int b = bx >> 7;                         // 128 tiles/batch
    int tile = bx & 127;
    int x0 = (tile >> 4) * 4;
    int y0 = ((tile >> 2) & 3) * 8;
    int z0 = (tile & 3) * 8;

    // prologue: stage taps 0 and 1 (2 groups in flight), overlapping halo load
    stage_weights(wB, 0, wsh_u32, tid);
    asm volatile("cp.async.commit_group;" ::: "memory");
    stage_weights(wB, 1, wsh_u32 + C_WBUF * 4, tid);
    asm volatile("cp.async.commit_group;" ::: "memory");

    // halo load: 6x10x10 rows x 64ch, zero-padded, tf32-preconverted,
    // optionally scaled by 1/max(cnt,1) (fused voxel averaging for conv1)
    for (int s = tid; s < C_HROWS * 16; s += 512) {
        int vox = s >> 4, c4 = s & 15;
        int hx = vox / 100;
        int r = vox - hx * 100;
        int hy = r / 10;
        int hz = r - hy * 10;
        int gx = x0 + hx - 1, gy = y0 + hy - 1, gz = z0 + hz - 1;
        float4 val = make_float4(0.f, 0.f, 0.f, 0.f);
        if ((unsigned)gx < 32u && (unsigned)gy < 32u && (unsigned)gz < 32u) {
            size_t gvox = (((size_t)b * 32 + gx) * 32 + gy) * 32 + gz;
            val = *reinterpret_cast<const float4*>(&gin[gvox * CH + c4 * 4]);
            if (cnt) {
                float inv = 1.0f / fmaxf(cnt[gvox], 1.0f);
                val.x *= inv; val.y *= inv; val.z *= inv; val.w *= inv;
            }
            val.x = to_tf32(val.x); val.y = to_tf32(val.y);
            val.z = to_tf32(val.z); val.w = to_tf32(val.w);
        }
        *reinterpret_cast<float4*>(&in_sh[vox * C_ISTR + c4 * 4]) = val;
    }

    int w = tid >> 5;
    int lane = tid & 31;
    int mp = w & 7;
    int och = w >> 3;
    int xl = mp >> 1;
    int yh = mp & 1;
    int g = lane >> 3, lr = lane & 7;

    int arow0 = xl * 100 + (4 * yh + (g & 1)) * 10 + lr;
    int arow1 = xl * 100 + (4 * yh + 2 + (g & 1)) * 10 + lr;
    uint32_t A0base = insh_u32 + (uint32_t)(arow0 * C_ISTR + 4 * (g >> 1)) * 4u;
    uint32_t A1base = insh_u32 + (uint32_t)(arow1 * C_ISTR + 4 * (g >> 1)) * 4u;
    uint32_t Bq0 = (uint32_t)(((och * 4 + (g >> 1)) * 8 + lr) * C_WSTR + 4 * (g & 1)) * 4u;
    uint32_t Bq1 = (uint32_t)(((och * 4 + 2 + (g >> 1)) * 8 + lr) * C_WSTR + 4 * (g & 1)) * 4u;

    float acc[2][4][4];
#pragma unroll
    for (int t = 0; t < 2; t++)
#pragma unroll
        for (int nb = 0; nb < 4; nb++)
#pragma unroll
            for (int j = 0; j < 4; j++) acc[t][nb][j] = 0.f;

    int slot = 0;                            // tap % 3
    for (int tap = 0; tap < 27; tap++) {
        if (tap < 26) {
            asm volatile("cp.async.wait_group 1;" ::: "memory");   // group 'tap' done
        } else {
            asm volatile("cp.async.wait_group 0;" ::: "memory");
        }
        __syncthreads();   // all data of group 'tap' visible; all warps done tap-1
        if (tap + 2 < 27) {
            // slot (tap+2)%3 == (tap-1)%3: its readers finished at the barrier
            int nslot = slot + 2 >= 3 ? slot - 1 : slot + 2;
            stage_weights(wB, tap + 2, wsh_u32 + (uint32_t)nslot * (C_WBUF * 4), tid);
            asm volatile("cp.async.commit_group;" ::: "memory");
        }

        int dxi = tap / 9;
        int rr9 = tap - dxi * 9;
        int dyi = rr9 / 3;
        int dzi = rr9 - dyi * 3;
        uint32_t tapoff = (uint32_t)((dxi * 100 + dyi * 10 + dzi) * C_ISTR) * 4u;
        uint32_t a0 = A0base + tapoff;
        uint32_t a1 = A1base + tapoff;
        uint32_t wb = wsh_u32 + (uint32_t)slot * (C_WBUF * 4);

#pragma unroll
        for (int kk = 0; kk < 8; kk++) {
            unsigned A0[4], A1[4], B0[4], B1[4];
            ldsm_x4(A0[0], A0[1], A0[2], A0[3], a0 + kk * 32);
            ldsm_x4(A1[0], A1[1], A1[2], A1[3], a1 + kk * 32);
            ldsm_x4(B0[0], B0[1], B0[2], B0[3], wb + Bq0 + kk * 32);
            ldsm_x4(B1[0], B1[1], B1[2], B1[3], wb + Bq1 + kk * 32);
            mma_tf32(acc[0][0][0], acc[0][0][1], acc[0][0][2], acc[0][0][3],
                     A0[0], A0[1], A0[2], A0[3], B0[0], B0[1]);
            mma_tf32(acc[0][1][0], acc[0][1][1], acc[0][1][2], acc[0][1][3],
                     A0[0], A0[1], A0[2], A0[3], B0[2], B0[3]);
            mma_tf32(acc[0][2][0], acc[0][2][1], acc[0][2][2], acc[0][2][3],
                     A0[0], A0[1], A0[2], A0[3], B1[0], B1[1]);
            mma_tf32(acc[0][3][0], acc[0][3][1], acc[0][3][2], acc[0][3][3],
                     A0[0], A0[1], A0[2], A0[3], B1[2], B1[3]);
            mma_tf32(acc[1][0][0], acc[1][0][1], acc[1][0][2], acc[1][0][3],
                     A1[0], A1[1], A1[2], A1[3], B0[0], B0[1]);
            mma_tf32(acc[1][1][0], acc[1][1][1], acc[1][1][2], acc[1][1][3],
                     A1[0], A1[1], A1[2], A1[3], B0[2], B0[3]);
            mma_tf32(acc[1][2][0], acc[1][2][1], acc[1][2][2], acc[1][2][3],
                     A1[0], A1[1], A1[2], A1[3], B1[0], B1[1]);
            mma_tf32(acc[1][3][0], acc[1][3][1], acc[1][3][2], acc[1][3][3],
                     A1[0], A1[1], A1[2], A1[3], B1[2], B1[3]);
        }
        slot = slot + 1 >= 3 ? 0 : slot + 1;
    }

    // epilogue
    int zq = lane >> 2;
    int kq = lane & 3;
    int Z = z0 + zq;
#pragma unroll
    for (int t = 0; t < 2; t++) {
        int p = 2 * yh + t;
        int Ylo = y0 + 2 * p;
        size_t base_lo = ((((size_t)b * 32 + (x0 + xl)) * 32 + Ylo) * 32 + Z) * CH;
        size_t base_hi = base_lo + 32 * CH;
#pragma unroll
        for (int nb = 0; nb < 4; nb++) {
            int oc = (och * 4 + nb) * 8 + 2 * kq;
            float2 bb = *reinterpret_cast<const float2*>(&biasE[oc]);
            float y00 = acc[t][nb][0] + bb.x;
            float y01 = acc[t][nb][1] + bb.y;
            float y10 = acc[t][nb][2] + bb.x;
            float y11 = acc[t][nb][3] + bb.y;
            y00 = (y00 >= 0.f) ? y00 : 0.1f * y00;
            y01 = (y01 >= 0.f) ? y01 : 0.1f * y01;
            y10 = (y10 >= 0.f) ? y10 : 0.1f * y10;
            y11 = (y11 >= 0.f) ? y11 : 0.1f * y11;
            *reinterpret_cast<float2*>(&gout[base_lo + oc]) = make_float2(y00, y01);
            *reinterpret_cast<float2*>(&gout[base_hi + oc]) = make_float2(y10, y11);
        }
    }
}

// ============ launch #7: trilinear devoxelize ===============================
__global__ void devox_kernel(float* __restrict__ out, const float* __restrict__ grid) {
    int n = blockIdx.x * 256 + threadIdx.x;
    int cg = blockIdx.y;
    int b = blockIdx.z;
    const float* vc = d_voxc + (size_t)b * 3 * NPTS;
    float cx = vc[n], cy = vc[NPTS + n], cz = vc[2 * NPTS + n];
    int ix0 = (int)floorf(cx), iy0 = (int)floorf(cy), iz0 = (int)floorf(cz);
    float fx = cx - (float)ix0, fy = cy - (float)iy0, fz = cz - (float)iz0;
    int ix1 = min(ix0 + 1, 31), iy1 = min(iy0 + 1, 31), iz1 = min(iz0 + 1, 31);
    float gx0 = 1.f - fx, gy0 = 1.f - fy, gz0 = 1.f - fz;

    const float* g = grid + ((size_t)b * NVOX) * CH + cg * 4;
    float4 acc = make_float4(0.f, 0.f, 0.f, 0.f);

#define CORNER(XI, YI, ZI, W)                                                        \
    {                                                                                \
        float4 cv = *reinterpret_cast<const float4*>(                                \
            &g[(size_t)(((XI) * 32 + (YI)) * 32 + (ZI)) * CH]);                      \
        float ww = (W);                                                              \
        acc.x += ww * cv.x; acc.y += ww * cv.y; acc.z += ww * cv.z; acc.w += ww * cv.w; \
    }
    CORNER(ix0, iy0, iz0, gx0 * gy0 * gz0)
    CORNER(ix0, iy0, iz1, gx0 * gy0 * fz)
    CORNER(ix0, iy1, iz0, gx0 * fy * gz0)
    CORNER(ix0, iy1, iz1, gx0 * fy * fz)
    CORNER(ix1, iy0, iz0, fx * gy0 * gz0)
    CORNER(ix1, iy0, iz1, fx * gy0 * fz)
    CORNER(ix1, iy1, iz0, fx * fy * gz0)
    CORNER(ix1, iy1, iz1, fx * fy * fz)
#undef CORNER

    size_t ob = ((size_t)b * CH + cg * 4) * NPTS + n;
    out[ob] = acc.x;
    out[ob + NPTS] = acc.y;
    out[ob + 2 * (size_t)NPTS] = acc.z;
    out[ob + 3 * (size_t)NPTS] = acc.w;
}

// ============ launch #8: echo coords ========================================
__global__ void copy_coords_kernel(float* __restrict__ out, const float* __restrict__ coords) {
    int t = blockIdx.x * 256 + threadIdx.x;
    reinterpret_cast<float4*>(out)[t] = reinterpret_cast<const float4*>(coords)[t];
}

// ---------------- launch ----------------------------------------------------
extern "C" void kernel_launch(void* const* d_in, const int* in_sizes, int n_in,
                              void* d_out, int out_size) {
    (void)in_sizes; (void)n_in; (void)out_size;
    const float* feats  = (const float*)d_in[0];
    const float* coords = (const float*)d_in[1];
    const float* w1  = (const float*)d_in[2];
    const float* b1  = (const float*)d_in[3];
    const float* g1  = (const float*)d_in[4];
    const float* be1 = (const float*)d_in[5];
    const float* m1  = (const float*)d_in[6];
    const float* v1  = (const float*)d_in[7];
    const float* w2  = (const float*)d_in[8];
    const float* b2  = (const float*)d_in[9];
    const float* g2  = (const float*)d_in[10];
    const float* be2 = (const float*)d_in[11];
    const float* m2  = (const float*)d_in[12];
    const float* v2  = (const float*)d_in[13];
    float* out = (float*)d_out;

    float *p_g0, *p_g1, *p_g2, *p_wB1, *p_wB2, *p_be1, *p_be2, *p_cnt;
    cudaGetSymbolAddress((void**)&p_g0, d_grid0);
    cudaGetSymbolAddress((void**)&p_g1, d_grid1);
    cudaGetSymbolAddress((void**)&p_g2, d_grid2);
    cudaGetSymbolAddress((void**)&p_wB1, d_wB1);
    cudaGetSymbolAddress((void**)&p_wB2, d_wB2);
    cudaGetSymbolAddress((void**)&p_be1, d_biasE1);
    cudaGetSymbolAddress((void**)&p_be2, d_biasE2);
    cudaGetSymbolAddress((void**)&p_cnt, d_cnt);

    cudaFuncSetAttribute(conv_tc_kernel, cudaFuncAttributeMaxDynamicSharedMemorySize, C_SMEM);

    fused_init_kernel<<<ZBLK + BATCH, 256>>>(coords);                          // 1
    voxelize_kernel<<<(BATCH * NPTS) / 256, 256>>>(coords);                    // 2
    trans_scatter_kernel<<<dim3(NPTS / 32, 2, BATCH), dim3(32, 8)>>>(feats);   // 3
    prep_kernel<<<2 * PBLK, 256>>>(w1, b1, g1, be1, m1, v1,                    // 4
                                   w2, b2, g2, be2, m2, v2);
    conv_tc_kernel<<<BATCH * 128, 512, C_SMEM>>>(p_g0, p_g1, p_wB1, p_be1, p_cnt); // 5
    conv_tc_kernel<<<BATCH * 128, 512, C_SMEM>>>(p_g1, p_g2, p_wB2, p_be2, nullptr); // 6 (ncu)
    devox_kernel<<<dim3(NPTS / 256, 16, BATCH), 256>>>(out, p_g2);             // 7
    copy_coords_kernel<<<(BATCH * 3 * NPTS / 4) / 256, 256>>>(                 // 8
        out + (size_t)BATCH * CH * NPTS, coords);
}

// round 10
// speedup vs baseline: 5.8073x; 1.4902x over previous
#include <cuda_runtime.h>
#include <cuda_fp16.h>
#include <cstdint>

#define BATCH 8
#define CH 64
#define NPTS 65536
#define RR 32
#define NVOX 32768  // 32^3

// ---------------- scratch (__device__ globals; no allocation allowed) ------
__device__ float d_mean[BATCH * 3];
__device__ float d_scale[BATCH];
__device__ float d_voxc[BATCH * 3 * NPTS];            // clipped voxel coords
__device__ int   d_idx[BATCH * NPTS];                 // per-point voxel index
__device__ float d_cnt[BATCH * NVOX];                 // per-voxel point counts
__device__ float d_grid0[(size_t)BATCH * NVOX * CH];  // scatter SUMS (not averaged)
__device__ float d_grid1[(size_t)BATCH * NVOX * CH];  // after conv1
__device__ float d_grid2[(size_t)BATCH * NVOX * CH];  // after conv2
__device__ __half d_wH1[27 * 64 * 64];                // [tap][oc][ic] fp16, BN folded
__device__ __half d_wH2[27 * 64 * 64];
__device__ float d_biasE1[64];
__device__ float d_biasE2[64];

// ---------------- helpers ---------------------------------------------------
__device__ __forceinline__ void mma_f16(float& d0, float& d1, float& d2, float& d3,
                                        unsigned a0, unsigned a1, unsigned a2, unsigned a3,
                                        unsigned b0, unsigned b1) {
    asm("mma.sync.aligned.m16n8k16.row.col.f32.f16.f16.f32 "
        "{%0,%1,%2,%3},{%4,%5,%6,%7},{%8,%9},{%0,%1,%2,%3};"
        : "+f"(d0), "+f"(d1), "+f"(d2), "+f"(d3)
        : "r"(a0), "r"(a1), "r"(a2), "r"(a3), "r"(b0), "r"(b1));
}
__device__ __forceinline__ void ldsm_x4(unsigned& r0, unsigned& r1, unsigned& r2,
                                        unsigned& r3, uint32_t addr) {
    asm volatile("ldmatrix.sync.aligned.m8n8.x4.shared.b16 {%0,%1,%2,%3}, [%4];"
                 : "=r"(r0), "=r"(r1), "=r"(r2), "=r"(r3) : "r"(addr));
}

// ============ launch #1: fused zero + mean/scale + weight prep ==============
#define ZBLK 16640
#define PBLK 432
__global__ void fused_init_kernel(const float* __restrict__ coords,
                                  const float* __restrict__ w1, const float* __restrict__ b1,
                                  const float* __restrict__ g1, const float* __restrict__ be1,
                                  const float* __restrict__ m1, const float* __restrict__ v1,
                                  const float* __restrict__ w2, const float* __restrict__ b2,
                                  const float* __restrict__ g2, const float* __restrict__ be2,
                                  const float* __restrict__ m2, const float* __restrict__ v2) {
    __shared__ float red[3][256];
    int blk = blockIdx.x;
    int tid = threadIdx.x;

    if (blk < ZBLK) {
        size_t t = (size_t)blk * 256 + tid;
        const size_t g4 = (size_t)BATCH * NVOX * CH / 4;
        float4 z = make_float4(0.f, 0.f, 0.f, 0.f);
        if (t < g4) {
            reinterpret_cast<float4*>(d_grid0)[t] = z;
        } else {
            size_t u = t - g4;
            if (u < (size_t)BATCH * NVOX / 4) reinterpret_cast<float4*>(d_cnt)[u] = z;
        }
        return;
    }
    if (blk < ZBLK + BATCH) {
        // mean + scale, one block per batch
        int b = blk - ZBLK;
        const float* cb = coords + (size_t)b * 3 * NPTS;
        float s0 = 0.f, s1 = 0.f, s2 = 0.f;
        for (int n = tid; n < NPTS; n += 256) {
            s0 += cb[n];
            s1 += cb[NPTS + n];
            s2 += cb[2 * NPTS + n];
        }
        red[0][tid] = s0; red[1][tid] = s1; red[2][tid] = s2;
        __syncthreads();
        for (int off = 128; off > 0; off >>= 1) {
            if (tid < off) {
                red[0][tid] += red[0][tid + off];
                red[1][tid] += red[1][tid + off];
                red[2][tid] += red[2][tid + off];
            }
            __syncthreads();
        }
        float m0 = red[0][0] / (float)NPTS;
        float m1 = red[1][0] / (float)NPTS;
        float m2 = red[2][0] / (float)NPTS;
        __syncthreads();
        float mx = 0.f;
        for (int n = tid; n < NPTS; n += 256) {
            float dx = cb[n] - m0;
            float dy = cb[NPTS + n] - m1;
            float dz = cb[2 * NPTS + n] - m2;
            mx = fmaxf(mx, dx * dx + dy * dy + dz * dz);
        }
        red[0][tid] = mx;
        __syncthreads();
        for (int off = 128; off > 0; off >>= 1) {
            if (tid < off) red[0][tid] = fmaxf(red[0][tid], red[0][tid + off]);
            __syncthreads();
        }
        if (tid == 0) {
            d_mean[b * 3 + 0] = m0;
            d_mean[b * 3 + 1] = m1;
            d_mean[b * 3 + 2] = m2;
            d_scale[b] = sqrtf(red[0][0]);
        }
        return;
    }
    // weight prep: fp16 [tap][oc][ic] with BN scale folded, + bias
    const float *w, *bs, *g, *be, *m, *v;
    __half* wH; float* biasE;
    int i;
    if (blk < ZBLK + BATCH + PBLK) {
        i = (blk - ZBLK - BATCH) * 256 + tid;
        w = w1; bs = b1; g = g1; be = be1; m = m1; v = v1; wH = d_wH1; biasE = d_biasE1;
    } else {
        i = (blk - ZBLK - BATCH - PBLK) * 256 + tid;
        w = w2; bs = b2; g = g2; be = be2; m = m2; v = v2; wH = d_wH2; biasE = d_biasE2;
    }
    if (i < 64) {
        float sc = g[i] * rsqrtf(v[i] + 1e-4f);
        biasE[i] = (bs[i] - m[i]) * sc + be[i];
    }
    if (i < 27 * 64 * 64) {
        int ic = i & 63;
        int oc = (i >> 6) & 63;
        int tap = i >> 12;
        float sc = g[oc] * rsqrtf(v[oc] + 1e-4f);
        wH[i] = __float2half_rn(w[(oc * 64 + ic) * 27 + tap] * sc);
    }
}

// ============ launch #2: voxelize coords -> voxc, idx, cnt ==================
__global__ void voxelize_kernel(const float* __restrict__ coords) {
    int t = blockIdx.x * 256 + threadIdx.x;       // [0, BATCH*NPTS)
    int b = t >> 16;
    int n = t & (NPTS - 1);
    const float* cb = coords + (size_t)b * 3 * NPTS;
    float m0 = d_mean[b * 3 + 0], m1 = d_mean[b * 3 + 1], m2 = d_mean[b * 3 + 2];
    float den = d_scale[b] * 2.0f;

    float vx = fminf(fmaxf(((cb[n]            - m0) / den + 0.5f) * 32.0f, 0.f), 31.f);
    float vy = fminf(fmaxf(((cb[NPTS + n]     - m1) / den + 0.5f) * 32.0f, 0.f), 31.f);
    float vz = fminf(fmaxf(((cb[2 * NPTS + n] - m2) / den + 0.5f) * 32.0f, 0.f), 31.f);

    float* vout = d_voxc + (size_t)b * 3 * NPTS;
    vout[n] = vx;
    vout[NPTS + n] = vy;
    vout[2 * NPTS + n] = vz;

    int ix = (int)rintf(vx);   // round-half-even, matches jnp.round
    int iy = (int)rintf(vy);
    int iz = (int)rintf(vz);
    int idx = (ix * 32 + iy) * 32 + iz;
    d_idx[t] = idx;
    atomicAdd(&d_cnt[b * NVOX + idx], 1.0f);
}

// ============ launch #3: transpose-scatter feats directly into grid0 ========
__global__ void trans_scatter_kernel(const float* __restrict__ f) {
    __shared__ float tile[32][33];     // [c][n]
    int b = blockIdx.z;
    int c0 = blockIdx.y * 32;
    int n0 = blockIdx.x * 32;
    int tx = threadIdx.x, ty = threadIdx.y;
    const float* fb = f + (size_t)b * CH * NPTS;
#pragma unroll
    for (int i = 0; i < 4; i++) {
        int c = c0 + ty + i * 8;
        tile[ty + i * 8][tx] = fb[(size_t)c * NPTS + n0 + tx];
    }
    __syncthreads();
    int n = n0 + tx;
    int idx = d_idx[b * NPTS + n];
    float* gb = &d_grid0[((size_t)b * NVOX + idx) * CH + c0 + ty * 4];
    float v0 = tile[ty * 4 + 0][tx];
    float v1 = tile[ty * 4 + 1][tx];
    float v2 = tile[ty * 4 + 2][tx];
    float v3 = tile[ty * 4 + 3][tx];
    asm volatile("red.global.add.v4.f32 [%0], {%1, %2, %3, %4};"
                 :: "l"(gb), "f"(v0), "f"(v1), "f"(v2), "f"(v3) : "memory");
}

// ============ launches #4/#5: conv — fp16 HMMA m32n32/warp, 2 CTAs/SM =======
// Tile 4x8x8 = 256 vox, 512 threads (16 warps), warp = m32 x n32, K=64.
// Halo 6x10x10 rows x 64ch fp16, row stride 72 halfs (144B: 16B-aligned,
// 4-bank step -> ldmatrix conflict-free). Weights [oc][ic] fp16, stride 72,
// 2-stage cp.async ring, one barrier per tap. conv1 fuses 1/cnt averaging.
#define C_HROWS 600
#define C_ISTRH 72                        // halfs per halo row
#define C_WROWH 72                        // halfs per weight row
#define C_INH (C_HROWS * C_ISTRH)         // 43200 halfs
#define C_WSTAGE (64 * C_WROWH)           // 4608 halfs per stage
#define C_SMEM ((C_INH + 2 * C_WSTAGE) * 2)  // 104832 bytes

__device__ __forceinline__ void stage_weights(const __half* __restrict__ wH, int tap,
                                              uint32_t dst_base, int tid) {
    // 64 rows x 128B; 512 chunks of 16B; one per thread
    int row = tid >> 3, ch = tid & 7;
    const __half* src = wH + tap * 4096 + row * 64 + ch * 8;
    uint32_t d = dst_base + (uint32_t)(row * 144 + ch * 16);
    asm volatile("cp.async.cg.shared.global [%0], [%1], 16;"
                 :: "r"(d), "l"(src) : "memory");
}

__global__ void __launch_bounds__(512, 2) conv_tc_kernel(const float* __restrict__ gin,
                                                         float* __restrict__ gout,
                                                         const __half* __restrict__ wH,
                                                         const float* __restrict__ biasE,
                                                         const float* __restrict__ cnt) {
    extern __shared__ __half shh[];
    __half* in_sh = shh;
    __half* w_sh = shh + C_INH;            // 2 stages
    uint32_t insh_u32 = (uint32_t)__cvta_generic_to_shared(in_sh);
    uint32_t wsh_u32 = (uint32_t)__cvta_generic_to_shared(w_sh);

    int tid = threadIdx.x;
    int bx = blockIdx.x;
    int b = bx >> 7;                       // 128 tiles/batch
    int tile = bx & 127;
    int x0 = (tile >> 4) * 4;
    int y0 = ((tile >> 2) & 3) * 8;
    int z0 = (tile & 3) * 8;

    // prologue: stage tap 0 (overlaps halo load)
    stage_weights(wH, 0, wsh_u32, tid);
    asm volatile("cp.async.commit_group;" ::: "memory");

    // halo: 6x10x10 rows x 64 ch, zero-pad, fp16; conv1 scales by 1/max(cnt,1)
    for (int s = tid; s < C_HROWS * 16; s += 512) {
        int vox = s >> 4, c4 = s & 15;
        int hx = vox / 100;
        int r = vox - hx * 100;
        int hy = r / 10;
        int hz = r - hy * 10;
        int gx = x0 + hx - 1, gy = y0 + hy - 1, gz = z0 + hz - 1;
        float4 val = make_float4(0.f, 0.f, 0.f, 0.f);
        if ((unsigned)gx < 32u && (unsigned)gy < 32u && (unsigned)gz < 32u) {
            size_t gvox = (((size_t)b * 32 + gx) * 32 + gy) * 32 + gz;
            val = *reinterpret_cast<const float4*>(&gin[gvox * CH + c4 * 4]);
            if (cnt) {
                float inv = 1.0f / fmaxf(cnt[gvox], 1.0f);
                val.x *= inv; val.y *= inv; val.z *= inv; val.w *= inv;
            }
        }
        __half2 h0 = __floats2half2_rn(val.x, val.y);
        __half2 h1 = __floats2half2_rn(val.z, val.w);
        __half* p = in_sh + vox * C_ISTRH + c4 * 4;
        *reinterpret_cast<__half2*>(p) = h0;
        *reinterpret_cast<__half2*>(p + 2) = h1;
    }

    int w = tid >> 5;                      // warp [0,16)
    int lane = tid & 31;
    int mp = w & 7;
    int och = w >> 3;                      // oc half (n32)
    int xl = mp >> 1;
    int yh = mp & 1;                       // y base = 4*yh
    int q = lane >> 3;                     // ldmatrix address group
    int lr = lane & 7;
    int yq = q & 1;                        // +row within y-pair
    int kq8 = q >> 1;                      // +16B (k8) selector

    // A lane base byte-offsets for the two m16 tiles (tap/kc added later)
    int arow0 = xl * 100 + (4 * yh + 0 + yq) * 10 + lr;
    int arow1 = xl * 100 + (4 * yh + 2 + yq) * 10 + lr;
    uint32_t A0base = insh_u32 + (uint32_t)(arow0 * 144 + kq8 * 16);
    uint32_t A1base = insh_u32 + (uint32_t)(arow1 * 144 + kq8 * 16);
    // B lane offsets within a weight stage: n16 groups h=0,1
    uint32_t B0off = (uint32_t)((och * 32 + 0 + yq * 8 + lr) * 144 + kq8 * 16);
    uint32_t B1off = (uint32_t)((och * 32 + 16 + yq * 8 + lr) * 144 + kq8 * 16);

    float acc[2][4][4];
#pragma unroll
    for (int t = 0; t < 2; t++)
#pragma unroll
        for (int nb = 0; nb < 4; nb++)
#pragma unroll
            for (int j = 0; j < 4; j++) acc[t][nb][j] = 0.f;

    int slot = 0;
    for (int tap = 0; tap < 27; tap++) {
        asm volatile("cp.async.wait_group 0;" ::: "memory");   // tap's weights in
        __syncthreads();   // visible to all; all warps done reading other slot
        if (tap + 1 < 27) {
            stage_weights(wH, tap + 1, wsh_u32 + (uint32_t)(slot ^ 1) * (C_WSTAGE * 2), tid);
            asm volatile("cp.async.commit_group;" ::: "memory");
        }

        int dxi = tap / 9;
        int rr9 = tap - dxi * 9;
        int dyi = rr9 / 3;
        int dzi = rr9 - dyi * 3;
        uint32_t tapoff = (uint32_t)((dxi * 100 + dyi * 10 + dzi) * 144);
        uint32_t a0 = A0base + tapoff;
        uint32_t a1 = A1base + tapoff;
        uint32_t wb = wsh_u32 + (uint32_t)slot * (C_WSTAGE * 2);

#pragma unroll
        for (int kc = 0; kc < 4; kc++) {
            unsigned A0[4], A1[4], Bl[4], Bh[4];
            ldsm_x4(A0[0], A0[1], A0[2], A0[3], a0 + kc * 32);
            ldsm_x4(A1[0], A1[1], A1[2], A1[3], a1 + kc * 32);
            ldsm_x4(Bl[0], Bl[1], Bl[2], Bl[3], wb + B0off + kc * 32);
            ldsm_x4(Bh[0], Bh[1], Bh[2], Bh[3], wb + B1off + kc * 32);
            // Bl: r0=nb0 k0-7, r1=nb1 k0-7, r2=nb0 k8-15, r3=nb1 k8-15
            mma_f16(acc[0][0][0], acc[0][0][1], acc[0][0][2], acc[0][0][3],
                    A0[0], A0[1], A0[2], A0[3], Bl[0], Bl[2]);
            mma_f16(acc[0][1][0], acc[0][1][1], acc[0][1][2], acc[0][1][3],
                    A0[0], A0[1], A0[2], A0[3], Bl[1], Bl[3]);
            mma_f16(acc[0][2][0], acc[0][2][1], acc[0][2][2], acc[0][2][3],
                    A0[0], A0[1], A0[2], A0[3], Bh[0], Bh[2]);
            mma_f16(acc[0][3][0], acc[0][3][1], acc[0][3][2], acc[0][3][3],
                    A0[0], A0[1], A0[2], A0[3], Bh[1], Bh[3]);
            mma_f16(acc[1][0][0], acc[1][0][1], acc[1][0][2], acc[1][0][3],
                    A1[0], A1[1], A1[2], A1[3], Bl[0], Bl[2]);
            mma_f16(acc[1][1][0], acc[1][1][1], acc[1][1][2], acc[1][1][3],
                    A1[0], A1[1], A1[2], A1[3], Bl[1], Bl[3]);
            mma_f16(acc[1][2][0], acc[1][2][1], acc[1][2][2], acc[1][2][3],
                    A1[0], A1[1], A1[2], A1[3], Bh[0], Bh[2]);
            mma_f16(acc[1][3][0], acc[1][3][1], acc[1][3][2], acc[1][3][3],
                    A1[0], A1[1], A1[2], A1[3], Bh[1], Bh[3]);
        }
        slot ^= 1;
    }

    // epilogue: c0/c1 -> (y=Y, z=lane/4, oc=nb*8+2kq); c2/c3 -> y=Y+1
    int zq = lane >> 2;
    int kq = lane & 3;
    int Z = z0 + zq;
#pragma unroll
    for (int t = 0; t < 2; t++) {
        int Ylo = y0 + 4 * yh + 2 * t;
        size_t base_lo = ((((size_t)b * 32 + (x0 + xl)) * 32 + Ylo) * 32 + Z) * CH;
        size_t base_hi = base_lo + 32 * CH;
#pragma unroll
        for (int nb = 0; nb < 4; nb++) {
            int oc = (och * 4 + nb) * 8 + 2 * kq;
            float2 bb = *reinterpret_cast<const float2*>(&biasE[oc]);
            float y00 = acc[t][nb][0] + bb.x;
            float y01 = acc[t][nb][1] + bb.y;
            float y10 = acc[t][nb][2] + bb.x;
            float y11 = acc[t][nb][3] + bb.y;
            y00 = (y00 >= 0.f) ? y00 : 0.1f * y00;
            y01 = (y01 >= 0.f) ? y01 : 0.1f * y01;
            y10 = (y10 >= 0.f) ? y10 : 0.1f * y10;
            y11 = (y11 >= 0.f) ? y11 : 0.1f * y11;
            *reinterpret_cast<float2*>(&gout[base_lo + oc]) = make_float2(y00, y01);
            *reinterpret_cast<float2*>(&gout[base_hi + oc]) = make_float2(y10, y11);
        }
    }
}

// ============ launch #6: trilinear devoxelize ===============================
__global__ void devox_kernel(float* __restrict__ out, const float* __restrict__ grid) {
    int n = blockIdx.x * 256 + threadIdx.x;
    int cg = blockIdx.y;
    int b = blockIdx.z;
    const float* vc = d_voxc + (size_t)b * 3 * NPTS;
    float cx = vc[n], cy = vc[NPTS + n], cz = vc[2 * NPTS + n];
    int ix0 = (int)floorf(cx), iy0 = (int)floorf(cy), iz0 = (int)floorf(cz);
    float fx = cx - (float)ix0, fy = cy - (float)iy0, fz = cz - (float)iz0;
    int ix1 = min(ix0 + 1, 31), iy1 = min(iy0 + 1, 31), iz1 = min(iz0 + 1, 31);
    float gx0 = 1.f - fx, gy0 = 1.f - fy, gz0 = 1.f - fz;

    const float* g = grid + ((size_t)b * NVOX) * CH + cg * 4;
    float4 acc = make_float4(0.f, 0.f, 0.f, 0.f);

#define CORNER(XI, YI, ZI, W)                                                        \
    {                                                                                \
        float4 cv = *reinterpret_cast<const float4*>(                                \
            &g[(size_t)(((XI) * 32 + (YI)) * 32 + (ZI)) * CH]);                      \
        float ww = (W);                                                              \
        acc.x += ww * cv.x; acc.y += ww * cv.y; acc.z += ww * cv.z; acc.w += ww * cv.w; \
    }
    CORNER(ix0, iy0, iz0, gx0 * gy0 * gz0)
    CORNER(ix0, iy0, iz1, gx0 * gy0 * fz)
    CORNER(ix0, iy1, iz0, gx0 * fy * gz0)
    CORNER(ix0, iy1, iz1, gx0 * fy * fz)
    CORNER(ix1, iy0, iz0, fx * gy0 * gz0)
    CORNER(ix1, iy0, iz1, fx * gy0 * fz)
    CORNER(ix1, iy1, iz0, fx * fy * gz0)
    CORNER(ix1, iy1, iz1, fx * fy * fz)
#undef CORNER

    size_t ob = ((size_t)b * CH + cg * 4) * NPTS + n;
    out[ob] = acc.x;
    out[ob + NPTS] = acc.y;
    out[ob + 2 * (size_t)NPTS] = acc.z;
    out[ob + 3 * (size_t)NPTS] = acc.w;
}

// ============ launch #7: echo coords ========================================
__global__ void copy_coords_kernel(float* __restrict__ out, const float* __restrict__ coords) {
    int t = blockIdx.x * 256 + threadIdx.x;
    reinterpret_cast<float4*>(out)[t] = reinterpret_cast<const float4*>(coords)[t];
}

// ---------------- launch ----------------------------------------------------
extern "C" void kernel_launch(void* const* d_in, const int* in_sizes, int n_in,
                              void* d_out, int out_size) {
    (void)in_sizes; (void)n_in; (void)out_size;
    const float* feats  = (const float*)d_in[0];
    const float* coords = (const float*)d_in[1];
    const float* w1  = (const float*)d_in[2];
    const float* b1  = (const float*)d_in[3];
    const float* g1  = (const float*)d_in[4];
    const float* be1 = (const float*)d_in[5];
    const float* m1  = (const float*)d_in[6];
    const float* v1  = (const float*)d_in[7];
    const float* w2  = (const float*)d_in[8];
    const float* b2  = (const float*)d_in[9];
    const float* g2  = (const float*)d_in[10];
    const float* be2 = (const float*)d_in[11];
    const float* m2  = (const float*)d_in[12];
    const float* v2  = (const float*)d_in[13];
    float* out = (float*)d_out;

    float *p_g0, *p_g1, *p_g2, *p_be1, *p_be2, *p_cnt;
    __half *p_wH1, *p_wH2;
    cudaGetSymbolAddress((void**)&p_g0, d_grid0);
    cudaGetSymbolAddress((void**)&p_g1, d_grid1);
    cudaGetSymbolAddress((void**)&p_g2, d_grid2);
    cudaGetSymbolAddress((void**)&p_wH1, d_wH1);
    cudaGetSymbolAddress((void**)&p_wH2, d_wH2);
    cudaGetSymbolAddress((void**)&p_be1, d_biasE1);
    cudaGetSymbolAddress((void**)&p_be2, d_biasE2);
    cudaGetSymbolAddress((void**)&p_cnt, d_cnt);

    cudaFuncSetAttribute(conv_tc_kernel, cudaFuncAttributeMaxDynamicSharedMemorySize, C_SMEM);

    fused_init_kernel<<<ZBLK + BATCH + 2 * PBLK, 256>>>(coords,                // 1
        w1, b1, g1, be1, m1, v1, w2, b2, g2, be2, m2, v2);
    voxelize_kernel<<<(BATCH * NPTS) / 256, 256>>>(coords);                    // 2
    trans_scatter_kernel<<<dim3(NPTS / 32, 2, BATCH), dim3(32, 8)>>>(feats);   // 3
    conv_tc_kernel<<<BATCH * 128, 512, C_SMEM>>>(p_g0, p_g1, p_wH1, p_be1, p_cnt);   // 4 (ncu)
    conv_tc_kernel<<<BATCH * 128, 512, C_SMEM>>>(p_g1, p_g2, p_wH2, p_be2, nullptr); // 5
    devox_kernel<<<dim3(NPTS / 256, 16, BATCH), 256>>>(out, p_g2);             // 6
    copy_coords_kernel<<<(BATCH * 3 * NPTS / 4) / 256, 256>>>(                 // 7
        out + (size_t)BATCH * CH * NPTS, coords);
}